// round 13
// baseline (speedup 1.0000x reference)
#include <cuda_runtime.h>
#include <cuda_bf16.h>
#include <cstdint>
#include <math.h>

// Problem constants
constexpr int B_   = 4;
constexpr int N_   = 2048;
constexpr int D_   = 1024;
constexpr int MTOT = B_ * N_;  // 8192

// ---------------- scratch (static __device__, allocation-free) ----------------
__device__ __align__(1024) __nv_bfloat16 g_Xh[(size_t)MTOT * D_];
__device__ __align__(1024) __nv_bfloat16 g_Xl[(size_t)MTOT * D_];
__device__ __align__(1024) __nv_bfloat16 g_Qh[(size_t)MTOT * D_];
__device__ __align__(1024) __nv_bfloat16 g_Ql[(size_t)MTOT * D_];
__device__ __align__(1024) __nv_bfloat16 g_Kh[(size_t)MTOT * D_];
__device__ __align__(1024) __nv_bfloat16 g_Kl[(size_t)MTOT * D_];
__device__ __align__(1024) __nv_bfloat16 g_Vh[(size_t)MTOT * D_];    // V row-major [m][e]
__device__ __align__(1024) __nv_bfloat16 g_Vl[(size_t)MTOT * D_];
__device__ __align__(1024) __nv_bfloat16 g_Vth[(size_t)D_ * MTOT];   // V^T [e][m]
__device__ __align__(1024) __nv_bfloat16 g_Vtl[(size_t)D_ * MTOT];
__device__ __align__(1024) __nv_bfloat16 g_Wqth[(size_t)D_ * D_];    // W^T [e][d]
__device__ __align__(1024) __nv_bfloat16 g_Wqtl[(size_t)D_ * D_];
__device__ __align__(1024) __nv_bfloat16 g_Wkth[(size_t)D_ * D_];
__device__ __align__(1024) __nv_bfloat16 g_Wktl[(size_t)D_ * D_];
__device__ __align__(1024) __nv_bfloat16 g_Wvth[(size_t)D_ * D_];
__device__ __align__(1024) __nv_bfloat16 g_Wvtl[(size_t)D_ * D_];
__device__ __align__(1024) float         g_S [(size_t)B_ * N_ * N_]; // 64 MB
__device__ __align__(1024) __nv_bfloat16 g_Ph[(size_t)B_ * N_ * N_];
__device__ __align__(1024) __nv_bfloat16 g_Pl[(size_t)B_ * N_ * N_];

// ---------------- helpers (plain sm_80-level PTX only; no 'a' features) -------
__device__ __forceinline__ uint32_t s2u(const void* p) {
    uint32_t a;
    asm("{ .reg .u64 t; cvta.to.shared.u64 t, %1; cvt.u32.u64 %0, t; }" : "=r"(a) : "l"(p));
    return a;
}
__device__ __forceinline__ void cpasync16(uint32_t dst, const void* src) {
    asm volatile("cp.async.cg.shared.global [%0], [%1], 16;" :: "r"(dst), "l"(src));
}
__device__ __forceinline__ void ldm4(uint32_t (&r)[4], uint32_t addr) {
    asm volatile("ldmatrix.sync.aligned.m8n8.x4.shared.b16 {%0,%1,%2,%3}, [%4];"
                 : "=r"(r[0]), "=r"(r[1]), "=r"(r[2]), "=r"(r[3]) : "r"(addr));
}
__device__ __forceinline__ void mma16816(float (&c)[4], const uint32_t* a,
                                         uint32_t b0, uint32_t b1) {
    asm volatile(
        "mma.sync.aligned.m16n8k16.row.col.f32.bf16.bf16.f32 "
        "{%0,%1,%2,%3}, {%4,%5,%6,%7}, {%8,%9}, {%0,%1,%2,%3};"
        : "+f"(c[0]), "+f"(c[1]), "+f"(c[2]), "+f"(c[3])
        : "r"(a[0]), "r"(a[1]), "r"(a[2]), "r"(a[3]), "r"(b0), "r"(b1));
}
// Tile row = 32 bf16 = 64B; swizzle 16B chunk index within row for conflict-free ldmatrix
__device__ __forceinline__ uint32_t swoff(int row, int kb) {
    return (uint32_t)(row * 64 + ((kb ^ ((row >> 1) & 3)) << 4));
}

constexpr int TILE_BYTES = 128 * 32 * 2;     // 8 KB: 128 rows x 32 bf16
constexpr int STAGES     = 3;
constexpr size_t SMEM_BYTES = (size_t)STAGES * 4 * TILE_BYTES;  // 96 KB -> 2 CTAs/SM

// ---------------- shared GEMM mainloop ----------------
// Computes the 128x128 split-bf16 NT GEMM for one block tile into acc.
__device__ __forceinline__ void gemm_mainloop(
    uint32_t base, int tid, int wid, int lid, int wm, int wn,
    const __nv_bfloat16* aH, const __nv_bfloat16* aL, int lda,
    const __nv_bfloat16* bH, const __nv_bfloat16* bL, int ldb,
    int Kd, float (&acc)[4][4][4])
{
    const __nv_bfloat16* srcs[4] = { aH, aL, bH, bL };
    const int ldsv[4] = { lda, lda, ldb, ldb };

    auto load_chunk = [&](int chunk, int stage) {
        #pragma unroll
        for (int p = 0; p < 4; p++) {
            const __nv_bfloat16* s = srcs[p] + chunk * 32;
            const int ld = ldsv[p];
            const uint32_t tb = base + (uint32_t)((stage * 4 + p) * TILE_BYTES);
            #pragma unroll
            for (int i = 0; i < 2; i++) {
                int o = i * 256 + tid;          // 512 chunks of 16B
                int r = o >> 2, kb = o & 3;
                cpasync16(tb + swoff(r, kb), s + (long)r * ld + kb * 8);
            }
        }
        asm volatile("cp.async.commit_group;" ::: "memory");
    };

    const int nk = Kd / 32;
    load_chunk(0, 0); load_chunk(1, 1);

    const int rA  = (lid & 7) + ((lid >> 3) & 1) * 8;  // ldmatrix row-in-16
    const int kbh = (lid >> 4) & 1;                    // ldmatrix k-half

    int stage = 0;      // stage of chunk k
    int pstage = 2;     // stage of chunk k+2 == stage of chunk k-1

    for (int k = 0; k < nk; k++) {
        if (k + 1 < nk) asm volatile("cp.async.wait_group 1;" ::: "memory");
        else            asm volatile("cp.async.wait_group 0;" ::: "memory");
        __syncthreads();
        // Barrier proves chunk k-1's compute finished everywhere; its stage
        // equals (k+2)%3 — free to refill now. ONE barrier per chunk.
        if (k + 2 < nk) load_chunk(k + 2, pstage);

        const uint32_t sb  = base + (uint32_t)(stage * 4 * TILE_BYTES);
        const uint32_t tAh = sb;
        const uint32_t tAl = sb + TILE_BYTES;
        const uint32_t tBh = sb + 2 * TILE_BYTES;
        const uint32_t tBl = sb + 3 * TILE_BYTES;

        #pragma unroll
        for (int p = 0; p < 2; p++) {            // two k16 steps per 32-chunk
            // All our fragment rows differ by multiples of 16, so the swizzle
            // XOR term (kb ^ (row>>1)&3) is uniform across them.
            const uint32_t kxor = (uint32_t)(((2 * p + kbh) ^ ((rA >> 1) & 3)) << 4);
            uint32_t fAh[4][4], fAl[4][4], fBh[2][4], fBl[2][4];
            #pragma unroll
            for (int i = 0; i < 4; i++) {
                const uint32_t rb = (uint32_t)((wm * 64 + i * 16 + rA) * 64);
                ldm4(fAh[i], tAh + rb + kxor);
                ldm4(fAl[i], tAl + rb + kxor);
            }
            #pragma unroll
            for (int q = 0; q < 2; q++) {
                const uint32_t rb = (uint32_t)((wn * 32 + q * 16 + rA) * 64);
                ldm4(fBh[q], tBh + rb + kxor);
                ldm4(fBl[q], tBl + rb + kxor);
            }
            // Three passes over all 16 accumulator tiles: RAW distance 16 MMAs.
            #pragma unroll
            for (int i = 0; i < 4; i++)
                #pragma unroll
                for (int nt = 0; nt < 4; nt++) {
                    const int q = nt >> 1, sx = nt & 1;
                    mma16816(acc[i][nt], fAh[i], fBh[q][sx], fBh[q][sx + 2]);
                }
            #pragma unroll
            for (int i = 0; i < 4; i++)
                #pragma unroll
                for (int nt = 0; nt < 4; nt++) {
                    const int q = nt >> 1, sx = nt & 1;
                    mma16816(acc[i][nt], fAh[i], fBl[q][sx], fBl[q][sx + 2]);
                }
            #pragma unroll
            for (int i = 0; i < 4; i++)
                #pragma unroll
                for (int nt = 0; nt < 4; nt++) {
                    const int q = nt >> 1, sx = nt & 1;
                    mma16816(acc[i][nt], fAl[i], fBh[q][sx], fBh[q][sx + 2]);
                }
        }
        stage  = (stage  == STAGES - 1) ? 0 : stage + 1;
        pstage = (pstage == STAGES - 1) ? 0 : pstage + 1;
    }
}

// ================= generic split-bf16 GEMM (used for PV) =================
// OUTMODE: 0 = fp32 C, 1 = split hi/lo bf16 C. BIASMODE: 0 none, 1 by col.
template<int OUTMODE, int BIASMODE>
__global__ void __launch_bounds__(256, 2)
tc_gemm(const __nv_bfloat16* __restrict__ Ah, const __nv_bfloat16* __restrict__ Al,
        int lda, long sA,
        const __nv_bfloat16* __restrict__ Bh, const __nv_bfloat16* __restrict__ Bl,
        int ldb, long sB,
        float* __restrict__ Cf, __nv_bfloat16* __restrict__ Ch, __nv_bfloat16* __restrict__ Cl,
        int ldc, long sC, const float* __restrict__ bias, int Kd)
{
    extern __shared__ __align__(128) char dsm[];
    const uint32_t base = s2u(dsm);
    const int tid = threadIdx.x, wid = tid >> 5, lid = tid & 31;
    const int wm = wid >> 2, wn = wid & 3;
    const int m0 = blockIdx.y * 128, n0 = blockIdx.x * 128;
    const long z = blockIdx.z;

    float acc[4][4][4];
    #pragma unroll
    for (int i = 0; i < 4; i++)
        #pragma unroll
        for (int t = 0; t < 4; t++)
            #pragma unroll
            for (int j = 0; j < 4; j++) acc[i][t][j] = 0.0f;

    gemm_mainloop(base, tid, wid, lid, wm, wn,
                  Ah + z * sA + (long)m0 * lda, Al + z * sA + (long)m0 * lda, lda,
                  Bh + z * sB + (long)n0 * ldb, Bl + z * sB + (long)n0 * ldb, ldb,
                  Kd, acc);

    #pragma unroll
    for (int i = 0; i < 4; i++)
        #pragma unroll
        for (int nt = 0; nt < 4; nt++) {
            const int row = m0 + wm * 64 + i * 16 + (lid >> 2);
            const int col = n0 + wn * 32 + nt * 8 + 2 * (lid & 3);
            float v0 = acc[i][nt][0], v1 = acc[i][nt][1];
            float v2 = acc[i][nt][2], v3 = acc[i][nt][3];
            if (BIASMODE == 1) {
                const float b0 = bias[col], b1 = bias[col + 1];
                v0 += b0; v1 += b1; v2 += b0; v3 += b1;
            }
            const long o0 = (long)row * ldc + col + z * sC;
            const long o1 = o0 + 8L * ldc;
            if (OUTMODE == 0) {
                *(float2*)(Cf + o0) = make_float2(v0, v1);
                *(float2*)(Cf + o1) = make_float2(v2, v3);
            } else {
                __nv_bfloat16 h0 = __float2bfloat16(v0), h1 = __float2bfloat16(v1);
                __nv_bfloat16 h2 = __float2bfloat16(v2), h3 = __float2bfloat16(v3);
                __nv_bfloat16 l0 = __float2bfloat16(v0 - __bfloat162float(h0));
                __nv_bfloat16 l1 = __float2bfloat16(v1 - __bfloat162float(h1));
                __nv_bfloat16 l2 = __float2bfloat16(v2 - __bfloat162float(h2));
                __nv_bfloat16 l3 = __float2bfloat16(v3 - __bfloat162float(h3));
                __nv_bfloat162 ph0; ph0.x = h0; ph0.y = h1;
                __nv_bfloat162 ph1; ph1.x = h2; ph1.y = h3;
                __nv_bfloat162 pl0; pl0.x = l0; pl0.y = l1;
                __nv_bfloat162 pl1; pl1.x = l2; pl1.y = l3;
                *(__nv_bfloat162*)(Ch + o0) = ph0;
                *(__nv_bfloat162*)(Ch + o1) = ph1;
                *(__nv_bfloat162*)(Cl + o0) = pl0;
                *(__nv_bfloat162*)(Cl + o1) = pl1;
            }
        }
}

// ===== S = QK^T GEMM with the V-transpose folded in as an extra grid slice ====
// grid (16, 16, B_+1): z < B_ -> S tile;  z == B_ -> 256 CTAs transpose V planes.
// The transpose rides DRAM that's idle during the compute-bound GEMM, removing
// the standalone 30us transpose launch from the critical path.
__global__ void __launch_bounds__(256, 2)
s_gemm_vt(const __nv_bfloat16* __restrict__ Qh, const __nv_bfloat16* __restrict__ Ql,
          const __nv_bfloat16* __restrict__ Kh, const __nv_bfloat16* __restrict__ Kl,
          float* __restrict__ S,
          const __nv_bfloat16* __restrict__ Vh, const __nv_bfloat16* __restrict__ Vl,
          __nv_bfloat16* __restrict__ Vth, __nv_bfloat16* __restrict__ Vtl)
{
    extern __shared__ __align__(128) char dsm[];
    const int tid = threadIdx.x;

    if (blockIdx.z == B_) {
        // ---- V transpose: 16384 32x32 subtiles over 2 planes, 64 per CTA ----
        __nv_bfloat16* ts = (__nv_bfloat16*)dsm;         // 32 x 33 staging
        const int c  = blockIdx.y * 16 + blockIdx.x;     // 0..255
        const int tx = tid & 31, ty = tid >> 5;          // 32 x 8
        for (int t = 0; t < 64; t++) {
            const int id = c * 64 + t;                   // 0..16383
            const __nv_bfloat16* V = (id < 8192) ? Vh : Vl;
            __nv_bfloat16*       T = (id < 8192) ? Vth : Vtl;
            const int rem = id & 8191;
            const int m0 = (rem >> 5) * 32;              // 0..8160
            const int e0 = (rem & 31) * 32;              // 0..992
            #pragma unroll
            for (int i = ty; i < 32; i += 8)
                ts[i * 33 + tx] = V[(long)(m0 + i) * D_ + e0 + tx];
            __syncthreads();
            #pragma unroll
            for (int i = ty; i < 32; i += 8)
                T[(long)(e0 + i) * MTOT + m0 + tx] = ts[tx * 33 + i];
            __syncthreads();
        }
        return;
    }

    // ---- S = Q K^T tile (identical to tc_gemm<0,0>) ----
    const uint32_t base = s2u(dsm);
    const int wid = tid >> 5, lid = tid & 31;
    const int wm = wid >> 2, wn = wid & 3;
    const int m0 = blockIdx.y * 128, n0 = blockIdx.x * 128;
    const long z = blockIdx.z;

    float acc[4][4][4];
    #pragma unroll
    for (int i = 0; i < 4; i++)
        #pragma unroll
        for (int t = 0; t < 4; t++)
            #pragma unroll
            for (int j = 0; j < 4; j++) acc[i][t][j] = 0.0f;

    const long sQ = (long)N_ * D_;
    gemm_mainloop(base, tid, wid, lid, wm, wn,
                  Qh + z * sQ + (long)m0 * D_, Ql + z * sQ + (long)m0 * D_, D_,
                  Kh + z * sQ + (long)n0 * D_, Kl + z * sQ + (long)n0 * D_, D_,
                  D_, acc);

    #pragma unroll
    for (int i = 0; i < 4; i++)
        #pragma unroll
        for (int nt = 0; nt < 4; nt++) {
            const int row = m0 + wm * 64 + i * 16 + (lid >> 2);
            const int col = n0 + wn * 32 + nt * 8 + 2 * (lid & 3);
            const long o0 = (long)row * N_ + col + z * (long)N_ * N_;
            const long o1 = o0 + 8L * N_;
            *(float2*)(S + o0) = make_float2(acc[i][nt][0], acc[i][nt][1]);
            *(float2*)(S + o1) = make_float2(acc[i][nt][2], acc[i][nt][3]);
        }
}

// ================= fused QKV projection: one launch, z picks {Q,K,V} ==========
__global__ void __launch_bounds__(256, 2)
qkv_gemm(const __nv_bfloat16* __restrict__ Xh, const __nv_bfloat16* __restrict__ Xl,
         const __nv_bfloat16* __restrict__ Wqh, const __nv_bfloat16* __restrict__ Wql,
         const __nv_bfloat16* __restrict__ Wkh, const __nv_bfloat16* __restrict__ Wkl,
         const __nv_bfloat16* __restrict__ Wvh, const __nv_bfloat16* __restrict__ Wvl,
         const float* __restrict__ bq, const float* __restrict__ bk,
         const float* __restrict__ bv,
         __nv_bfloat16* __restrict__ Qh, __nv_bfloat16* __restrict__ Ql,
         __nv_bfloat16* __restrict__ Kh, __nv_bfloat16* __restrict__ Kl,
         __nv_bfloat16* __restrict__ Vh, __nv_bfloat16* __restrict__ Vl)
{
    extern __shared__ __align__(128) char dsm[];
    const uint32_t base = s2u(dsm);
    const int tid = threadIdx.x, wid = tid >> 5, lid = tid & 31;
    const int wm = wid >> 2, wn = wid & 3;
    const int m0 = blockIdx.y * 128, n0 = blockIdx.x * 128;
    const int zz = blockIdx.z;

    const __nv_bfloat16* Bh = (zz == 0) ? Wqh : (zz == 1) ? Wkh : Wvh;
    const __nv_bfloat16* Bl = (zz == 0) ? Wql : (zz == 1) ? Wkl : Wvl;
    const float* bias       = (zz == 0) ? bq  : (zz == 1) ? bk  : bv;
    __nv_bfloat16* Ch       = (zz == 0) ? Qh  : (zz == 1) ? Kh  : Vh;
    __nv_bfloat16* Cl       = (zz == 0) ? Ql  : (zz == 1) ? Kl  : Vl;

    float acc[4][4][4];
    #pragma unroll
    for (int i = 0; i < 4; i++)
        #pragma unroll
        for (int t = 0; t < 4; t++)
            #pragma unroll
            for (int j = 0; j < 4; j++) acc[i][t][j] = 0.0f;

    gemm_mainloop(base, tid, wid, lid, wm, wn,
                  Xh + (long)m0 * D_, Xl + (long)m0 * D_, D_,
                  Bh + (long)n0 * D_, Bl + (long)n0 * D_, D_,
                  D_, acc);

    #pragma unroll
    for (int i = 0; i < 4; i++)
        #pragma unroll
        for (int nt = 0; nt < 4; nt++) {
            const int row = m0 + wm * 64 + i * 16 + (lid >> 2);
            const int col = n0 + wn * 32 + nt * 8 + 2 * (lid & 3);
            const float b0 = bias[col], b1 = bias[col + 1];
            float v0 = acc[i][nt][0] + b0, v1 = acc[i][nt][1] + b1;
            float v2 = acc[i][nt][2] + b0, v3 = acc[i][nt][3] + b1;
            const long o0 = (long)row * D_ + col;
            const long o1 = o0 + 8L * D_;
            __nv_bfloat16 h0 = __float2bfloat16(v0), h1 = __float2bfloat16(v1);
            __nv_bfloat16 h2 = __float2bfloat16(v2), h3 = __float2bfloat16(v3);
            __nv_bfloat16 l0 = __float2bfloat16(v0 - __bfloat162float(h0));
            __nv_bfloat16 l1 = __float2bfloat16(v1 - __bfloat162float(h1));
            __nv_bfloat16 l2 = __float2bfloat16(v2 - __bfloat162float(h2));
            __nv_bfloat16 l3 = __float2bfloat16(v3 - __bfloat162float(h3));
            __nv_bfloat162 ph0; ph0.x = h0; ph0.y = h1;
            __nv_bfloat162 ph1; ph1.x = h2; ph1.y = h3;
            __nv_bfloat162 pl0; pl0.x = l0; pl0.y = l1;
            __nv_bfloat162 pl1; pl1.x = l2; pl1.y = l3;
            *(__nv_bfloat162*)(Ch + o0) = ph0;
            *(__nv_bfloat162*)(Ch + o1) = ph1;
            *(__nv_bfloat162*)(Cl + o0) = pl0;
            *(__nv_bfloat162*)(Cl + o1) = pl1;
        }
}

// ================= prep kernels =================
__global__ void __launch_bounds__(256)
split_x_kernel(const float* __restrict__ X, __nv_bfloat16* __restrict__ Xh,
               __nv_bfloat16* __restrict__ Xl)
{
    const long i = ((long)blockIdx.x * 256 + threadIdx.x) * 4;
    float4 v = *(const float4*)(X + i);
    float vv[4] = { v.x, v.y, v.z, v.w };
    __nv_bfloat16 h[4], l[4];
    #pragma unroll
    for (int j = 0; j < 4; j++) {
        h[j] = __float2bfloat16(vv[j]);
        l[j] = __float2bfloat16(vv[j] - __bfloat162float(h[j]));
    }
    __nv_bfloat162 h01, h23, l01, l23;
    h01.x = h[0]; h01.y = h[1]; h23.x = h[2]; h23.y = h[3];
    l01.x = l[0]; l01.y = l[1]; l23.x = l[2]; l23.y = l[3];
    *(__nv_bfloat162*)(Xh + i)     = h01;
    *(__nv_bfloat162*)(Xh + i + 2) = h23;
    *(__nv_bfloat162*)(Xl + i)     = l01;
    *(__nv_bfloat162*)(Xl + i + 2) = l23;
}

// Transpose + split 1024x1024 weights: T[e][d] = W[d][e]
__global__ void __launch_bounds__(256)
transpose_split_kernel(const float* __restrict__ W0, const float* __restrict__ W1,
                       const float* __restrict__ W2,
                       __nv_bfloat16* __restrict__ T0h, __nv_bfloat16* __restrict__ T0l,
                       __nv_bfloat16* __restrict__ T1h, __nv_bfloat16* __restrict__ T1l,
                       __nv_bfloat16* __restrict__ T2h, __nv_bfloat16* __restrict__ T2l)
{
    __shared__ float t[32][33];
    const float* W = (blockIdx.z == 0) ? W0 : (blockIdx.z == 1) ? W1 : W2;
    __nv_bfloat16* Th = (blockIdx.z == 0) ? T0h : (blockIdx.z == 1) ? T1h : T2h;
    __nv_bfloat16* Tl = (blockIdx.z == 0) ? T0l : (blockIdx.z == 1) ? T1l : T2l;

    const int tx = threadIdx.x, ty = threadIdx.y;       // block 32x8
    const int e = blockIdx.x * 32 + tx;
    const int d0 = blockIdx.y * 32;
    #pragma unroll
    for (int i = ty; i < 32; i += 8)
        t[i][tx] = W[(long)(d0 + i) * D_ + e];
    __syncthreads();
    const int eo = blockIdx.x * 32;
    const int d = d0 + tx;
    #pragma unroll
    for (int i = ty; i < 32; i += 8) {
        float w = t[tx][i];
        __nv_bfloat16 h = __float2bfloat16(w);
        __nv_bfloat16 l = __float2bfloat16(w - __bfloat162float(h));
        Th[(long)(eo + i) * D_ + d] = h;
        Tl[(long)(eo + i) * D_ + d] = l;
    }
}

// Row softmax over S (length 2048), write split-bf16 P.
__global__ void __launch_bounds__(256)
softmax_split_kernel(const float* __restrict__ S, __nv_bfloat16* __restrict__ Ph,
                     __nv_bfloat16* __restrict__ Pl)
{
    const long row = blockIdx.x;
    const float* p = S + row * (long)N_;
    const int tid = threadIdx.x;

    float v[8];
    float mx = -1e30f;
    #pragma unroll
    for (int i = 0; i < 8; i++) { v[i] = p[tid + i * 256]; mx = fmaxf(mx, v[i]); }

    __shared__ float redm[8], reds[8];
    #pragma unroll
    for (int o = 16; o; o >>= 1) mx = fmaxf(mx, __shfl_xor_sync(0xffffffffu, mx, o));
    if ((tid & 31) == 0) redm[tid >> 5] = mx;
    __syncthreads();
    if (tid == 0) {
        float m = redm[0];
        #pragma unroll
        for (int i = 1; i < 8; i++) m = fmaxf(m, redm[i]);
        redm[0] = m;
    }
    __syncthreads();
    mx = redm[0];

    float s = 0.0f;
    #pragma unroll
    for (int i = 0; i < 8; i++) { v[i] = __expf(v[i] - mx); s += v[i]; }
    #pragma unroll
    for (int o = 16; o; o >>= 1) s += __shfl_xor_sync(0xffffffffu, s, o);
    if ((tid & 31) == 0) reds[tid >> 5] = s;
    __syncthreads();
    if (tid == 0) {
        float m = 0.0f;
        #pragma unroll
        for (int i = 0; i < 8; i++) m += reds[i];
        reds[0] = m;
    }
    __syncthreads();
    const float inv = 1.0f / reds[0];

    #pragma unroll
    for (int i = 0; i < 8; i++) {
        float w = v[i] * inv;
        __nv_bfloat16 h = __float2bfloat16(w);
        __nv_bfloat16 l = __float2bfloat16(w - __bfloat162float(h));
        Ph[row * (long)N_ + tid + i * 256] = h;
        Pl[row * (long)N_ + tid + i * 256] = l;
    }
}

// ================= host glue =================
extern "C" void kernel_launch(void* const* d_in, const int* in_sizes, int n_in,
                              void* d_out, int out_size)
{
    const float* X  = (const float*)d_in[0];
    const float* Wq = (const float*)d_in[1];
    const float* bq = (const float*)d_in[2];
    const float* Wk = (const float*)d_in[3];
    const float* bk = (const float*)d_in[4];
    const float* Wv = (const float*)d_in[5];
    const float* bv = (const float*)d_in[6];
    float* out = (float*)d_out;

    __nv_bfloat16 *Xh, *Xl, *Qh, *Ql, *Kh, *Kl, *Vh, *Vl, *Vth, *Vtl;
    __nv_bfloat16 *Wqth, *Wqtl, *Wkth, *Wktl, *Wvth, *Wvtl, *Ph, *Pl;
    float* S;
    cudaGetSymbolAddress((void**)&Xh, g_Xh);   cudaGetSymbolAddress((void**)&Xl, g_Xl);
    cudaGetSymbolAddress((void**)&Qh, g_Qh);   cudaGetSymbolAddress((void**)&Ql, g_Ql);
    cudaGetSymbolAddress((void**)&Kh, g_Kh);   cudaGetSymbolAddress((void**)&Kl, g_Kl);
    cudaGetSymbolAddress((void**)&Vh, g_Vh);   cudaGetSymbolAddress((void**)&Vl, g_Vl);
    cudaGetSymbolAddress((void**)&Vth, g_Vth); cudaGetSymbolAddress((void**)&Vtl, g_Vtl);
    cudaGetSymbolAddress((void**)&Wqth, g_Wqth); cudaGetSymbolAddress((void**)&Wqtl, g_Wqtl);
    cudaGetSymbolAddress((void**)&Wkth, g_Wkth); cudaGetSymbolAddress((void**)&Wktl, g_Wktl);
    cudaGetSymbolAddress((void**)&Wvth, g_Wvth); cudaGetSymbolAddress((void**)&Wvtl, g_Wvtl);
    cudaGetSymbolAddress((void**)&Ph, g_Ph);   cudaGetSymbolAddress((void**)&Pl, g_Pl);
    cudaGetSymbolAddress((void**)&S, g_S);

    cudaFuncSetAttribute((const void*)qkv_gemm,      cudaFuncAttributeMaxDynamicSharedMemorySize, (int)SMEM_BYTES);
    cudaFuncSetAttribute((const void*)s_gemm_vt,     cudaFuncAttributeMaxDynamicSharedMemorySize, (int)SMEM_BYTES);
    cudaFuncSetAttribute((const void*)tc_gemm<0, 0>, cudaFuncAttributeMaxDynamicSharedMemorySize, (int)SMEM_BYTES);

    dim3 blk(256);

    // 0) split X, transpose+split weights
    split_x_kernel<<<(MTOT * D_) / 1024, 256>>>(X, Xh, Xl);
    transpose_split_kernel<<<dim3(32, 32, 3), dim3(32, 8)>>>(
        Wq, Wk, Wv, Wqth, Wqtl, Wkth, Wktl, Wvth, Wvtl);

    // 1) fused QKV projection: one launch, 1536 CTAs (z = q/k/v)
    qkv_gemm<<<dim3(8, 64, 3), blk, SMEM_BYTES>>>(
        Xh, Xl, Wqth, Wqtl, Wkth, Wktl, Wvth, Wvtl,
        bq, bk, bv, Qh, Ql, Kh, Kl, Vh, Vl);

    // 2) S = Q K^T per batch (fp32) + V transpose folded in (z == B_)
    s_gemm_vt<<<dim3(16, 16, B_ + 1), blk, SMEM_BYTES>>>(
        Qh, Ql, Kh, Kl, S, Vh, Vl, Vth, Vtl);

    // 3) softmax + split P
    softmax_split_kernel<<<B_ * N_, 256>>>(S, Ph, Pl);

    // 4) out = P V per batch (NT against V^T, fp32 out)
    tc_gemm<0, 0><<<dim3(8, 16, B_), blk, SMEM_BYTES>>>(
        Ph, Pl, N_, (long)N_ * N_, Vth, Vtl, MTOT, (long)N_,
        out, nullptr, nullptr, D_, (long)N_ * D_, nullptr, N_);
}

// round 14
// speedup vs baseline: 1.0472x; 1.0472x over previous
#include <cuda_runtime.h>
#include <cuda_bf16.h>
#include <cstdint>
#include <math.h>

// Problem constants
constexpr int B_   = 4;
constexpr int N_   = 2048;
constexpr int D_   = 1024;
constexpr int MTOT = B_ * N_;  // 8192

// ---------------- scratch (static __device__, allocation-free) ----------------
__device__ __align__(1024) __nv_bfloat16 g_Xh[(size_t)MTOT * D_];
__device__ __align__(1024) __nv_bfloat16 g_Xl[(size_t)MTOT * D_];
__device__ __align__(1024) __nv_bfloat16 g_Qh[(size_t)MTOT * D_];
__device__ __align__(1024) __nv_bfloat16 g_Ql[(size_t)MTOT * D_];
__device__ __align__(1024) __nv_bfloat16 g_Kh[(size_t)MTOT * D_];
__device__ __align__(1024) __nv_bfloat16 g_Kl[(size_t)MTOT * D_];
__device__ __align__(1024) __nv_bfloat16 g_Vth[(size_t)D_ * MTOT];   // V^T [e][m]
__device__ __align__(1024) __nv_bfloat16 g_Vtl[(size_t)D_ * MTOT];
__device__ __align__(1024) __nv_bfloat16 g_Wqth[(size_t)D_ * D_];    // W^T [e][d]
__device__ __align__(1024) __nv_bfloat16 g_Wqtl[(size_t)D_ * D_];
__device__ __align__(1024) __nv_bfloat16 g_Wkth[(size_t)D_ * D_];
__device__ __align__(1024) __nv_bfloat16 g_Wktl[(size_t)D_ * D_];
__device__ __align__(1024) __nv_bfloat16 g_Wvth[(size_t)D_ * D_];
__device__ __align__(1024) __nv_bfloat16 g_Wvtl[(size_t)D_ * D_];
__device__ __align__(1024) float         g_S [(size_t)B_ * N_ * N_]; // 64 MB
__device__ __align__(1024) __nv_bfloat16 g_Ph[(size_t)B_ * N_ * N_];
__device__ __align__(1024) __nv_bfloat16 g_Pl[(size_t)B_ * N_ * N_];

// ---------------- helpers (plain sm_80-level PTX only; no 'a' features) -------
__device__ __forceinline__ uint32_t s2u(const void* p) {
    uint32_t a;
    asm("{ .reg .u64 t; cvta.to.shared.u64 t, %1; cvt.u32.u64 %0, t; }" : "=r"(a) : "l"(p));
    return a;
}
__device__ __forceinline__ void cpasync16(uint32_t dst, const void* src) {
    asm volatile("cp.async.cg.shared.global [%0], [%1], 16;" :: "r"(dst), "l"(src));
}
__device__ __forceinline__ void ldm4(uint32_t (&r)[4], uint32_t addr) {
    asm volatile("ldmatrix.sync.aligned.m8n8.x4.shared.b16 {%0,%1,%2,%3}, [%4];"
                 : "=r"(r[0]), "=r"(r[1]), "=r"(r[2]), "=r"(r[3]) : "r"(addr));
}
__device__ __forceinline__ void mma16816(float (&c)[4], const uint32_t* a,
                                         uint32_t b0, uint32_t b1) {
    asm volatile(
        "mma.sync.aligned.m16n8k16.row.col.f32.bf16.bf16.f32 "
        "{%0,%1,%2,%3}, {%4,%5,%6,%7}, {%8,%9}, {%0,%1,%2,%3};"
        : "+f"(c[0]), "+f"(c[1]), "+f"(c[2]), "+f"(c[3])
        : "r"(a[0]), "r"(a[1]), "r"(a[2]), "r"(a[3]), "r"(b0), "r"(b1));
}
// Tile row = 32 bf16 = 64B; swizzle 16B chunk index within row for conflict-free ldmatrix
__device__ __forceinline__ uint32_t swoff(int row, int kb) {
    return (uint32_t)(row * 64 + ((kb ^ ((row >> 1) & 3)) << 4));
}

constexpr int TILE_BYTES = 128 * 32 * 2;     // 8 KB: 128 rows x 32 bf16
constexpr int STAGES     = 3;
constexpr size_t SMEM_BYTES = (size_t)STAGES * 4 * TILE_BYTES;  // 96 KB -> 2 CTAs/SM

// ---------------- shared GEMM mainloop ----------------
// Computes the 128x128 split-bf16 NT GEMM for one block tile into acc.
__device__ __forceinline__ void gemm_mainloop(
    uint32_t base, int tid, int wid, int lid, int wm, int wn,
    const __nv_bfloat16* aH, const __nv_bfloat16* aL, int lda,
    const __nv_bfloat16* bH, const __nv_bfloat16* bL, int ldb,
    int Kd, float (&acc)[4][4][4])
{
    const __nv_bfloat16* srcs[4] = { aH, aL, bH, bL };
    const int ldsv[4] = { lda, lda, ldb, ldb };

    auto load_chunk = [&](int chunk, int stage) {
        #pragma unroll
        for (int p = 0; p < 4; p++) {
            const __nv_bfloat16* s = srcs[p] + chunk * 32;
            const int ld = ldsv[p];
            const uint32_t tb = base + (uint32_t)((stage * 4 + p) * TILE_BYTES);
            #pragma unroll
            for (int i = 0; i < 2; i++) {
                int o = i * 256 + tid;          // 512 chunks of 16B
                int r = o >> 2, kb = o & 3;
                cpasync16(tb + swoff(r, kb), s + (long)r * ld + kb * 8);
            }
        }
        asm volatile("cp.async.commit_group;" ::: "memory");
    };

    const int nk = Kd / 32;
    load_chunk(0, 0); load_chunk(1, 1);

    const int rA  = (lid & 7) + ((lid >> 3) & 1) * 8;  // ldmatrix row-in-16
    const int kbh = (lid >> 4) & 1;                    // ldmatrix k-half

    int stage = 0;      // stage of chunk k
    int pstage = 2;     // stage of chunk k+2 == stage of chunk k-1

    for (int k = 0; k < nk; k++) {
        if (k + 1 < nk) asm volatile("cp.async.wait_group 1;" ::: "memory");
        else            asm volatile("cp.async.wait_group 0;" ::: "memory");
        __syncthreads();
        // Barrier proves chunk k-1's compute finished everywhere; its stage
        // equals (k+2)%3 — free to refill now. ONE barrier per chunk.
        if (k + 2 < nk) load_chunk(k + 2, pstage);

        const uint32_t sb  = base + (uint32_t)(stage * 4 * TILE_BYTES);
        const uint32_t tAh = sb;
        const uint32_t tAl = sb + TILE_BYTES;
        const uint32_t tBh = sb + 2 * TILE_BYTES;
        const uint32_t tBl = sb + 3 * TILE_BYTES;

        #pragma unroll
        for (int p = 0; p < 2; p++) {            // two k16 steps per 32-chunk
            // All our fragment rows differ by multiples of 16, so the swizzle
            // XOR term (kb ^ (row>>1)&3) is uniform across them.
            const uint32_t kxor = (uint32_t)(((2 * p + kbh) ^ ((rA >> 1) & 3)) << 4);
            uint32_t fAh[4][4], fAl[4][4], fBh[2][4], fBl[2][4];
            #pragma unroll
            for (int i = 0; i < 4; i++) {
                const uint32_t rb = (uint32_t)((wm * 64 + i * 16 + rA) * 64);
                ldm4(fAh[i], tAh + rb + kxor);
                ldm4(fAl[i], tAl + rb + kxor);
            }
            #pragma unroll
            for (int q = 0; q < 2; q++) {
                const uint32_t rb = (uint32_t)((wn * 32 + q * 16 + rA) * 64);
                ldm4(fBh[q], tBh + rb + kxor);
                ldm4(fBl[q], tBl + rb + kxor);
            }
            // Three passes over all 16 accumulator tiles: RAW distance 16 MMAs.
            #pragma unroll
            for (int i = 0; i < 4; i++)
                #pragma unroll
                for (int nt = 0; nt < 4; nt++) {
                    const int q = nt >> 1, sx = nt & 1;
                    mma16816(acc[i][nt], fAh[i], fBh[q][sx], fBh[q][sx + 2]);
                }
            #pragma unroll
            for (int i = 0; i < 4; i++)
                #pragma unroll
                for (int nt = 0; nt < 4; nt++) {
                    const int q = nt >> 1, sx = nt & 1;
                    mma16816(acc[i][nt], fAh[i], fBl[q][sx], fBl[q][sx + 2]);
                }
            #pragma unroll
            for (int i = 0; i < 4; i++)
                #pragma unroll
                for (int nt = 0; nt < 4; nt++) {
                    const int q = nt >> 1, sx = nt & 1;
                    mma16816(acc[i][nt], fAl[i], fBh[q][sx], fBh[q][sx + 2]);
                }
        }
        stage  = (stage  == STAGES - 1) ? 0 : stage + 1;
        pstage = (pstage == STAGES - 1) ? 0 : pstage + 1;
    }
}

// ================= generic split-bf16 GEMM (S = QK^T, out = PV) =================
// OUTMODE: 0 = fp32 C, 1 = split hi/lo bf16 C. BIASMODE: 0 none, 1 by col.
template<int OUTMODE, int BIASMODE>
__global__ void __launch_bounds__(256, 2)
tc_gemm(const __nv_bfloat16* __restrict__ Ah, const __nv_bfloat16* __restrict__ Al,
        int lda, long sA,
        const __nv_bfloat16* __restrict__ Bh, const __nv_bfloat16* __restrict__ Bl,
        int ldb, long sB,
        float* __restrict__ Cf, __nv_bfloat16* __restrict__ Ch, __nv_bfloat16* __restrict__ Cl,
        int ldc, long sC, const float* __restrict__ bias, int Kd)
{
    extern __shared__ __align__(128) char dsm[];
    const uint32_t base = s2u(dsm);
    const int tid = threadIdx.x, wid = tid >> 5, lid = tid & 31;
    const int wm = wid >> 2, wn = wid & 3;
    const int m0 = blockIdx.y * 128, n0 = blockIdx.x * 128;
    const long z = blockIdx.z;

    float acc[4][4][4];
    #pragma unroll
    for (int i = 0; i < 4; i++)
        #pragma unroll
        for (int t = 0; t < 4; t++)
            #pragma unroll
            for (int j = 0; j < 4; j++) acc[i][t][j] = 0.0f;

    gemm_mainloop(base, tid, wid, lid, wm, wn,
                  Ah + z * sA + (long)m0 * lda, Al + z * sA + (long)m0 * lda, lda,
                  Bh + z * sB + (long)n0 * ldb, Bl + z * sB + (long)n0 * ldb, ldb,
                  Kd, acc);

    #pragma unroll
    for (int i = 0; i < 4; i++)
        #pragma unroll
        for (int nt = 0; nt < 4; nt++) {
            const int row = m0 + wm * 64 + i * 16 + (lid >> 2);
            const int col = n0 + wn * 32 + nt * 8 + 2 * (lid & 3);
            float v0 = acc[i][nt][0], v1 = acc[i][nt][1];
            float v2 = acc[i][nt][2], v3 = acc[i][nt][3];
            if (BIASMODE == 1) {
                const float b0 = bias[col], b1 = bias[col + 1];
                v0 += b0; v1 += b1; v2 += b0; v3 += b1;
            }
            const long o0 = (long)row * ldc + col + z * sC;
            const long o1 = o0 + 8L * ldc;
            if (OUTMODE == 0) {
                *(float2*)(Cf + o0) = make_float2(v0, v1);
                *(float2*)(Cf + o1) = make_float2(v2, v3);
            } else {
                __nv_bfloat16 h0 = __float2bfloat16(v0), h1 = __float2bfloat16(v1);
                __nv_bfloat16 h2 = __float2bfloat16(v2), h3 = __float2bfloat16(v3);
                __nv_bfloat16 l0 = __float2bfloat16(v0 - __bfloat162float(h0));
                __nv_bfloat16 l1 = __float2bfloat16(v1 - __bfloat162float(h1));
                __nv_bfloat16 l2 = __float2bfloat16(v2 - __bfloat162float(h2));
                __nv_bfloat16 l3 = __float2bfloat16(v3 - __bfloat162float(h3));
                __nv_bfloat162 ph0; ph0.x = h0; ph0.y = h1;
                __nv_bfloat162 ph1; ph1.x = h2; ph1.y = h3;
                __nv_bfloat162 pl0; pl0.x = l0; pl0.y = l1;
                __nv_bfloat162 pl1; pl1.x = l2; pl1.y = l3;
                *(__nv_bfloat162*)(Ch + o0) = ph0;
                *(__nv_bfloat162*)(Ch + o1) = ph1;
                *(__nv_bfloat162*)(Cl + o0) = pl0;
                *(__nv_bfloat162*)(Cl + o1) = pl1;
            }
        }
}

// ===== fused QKV projection: one launch; z=0 -> Q, z=1 -> K, z=2 -> V^T =======
// z<2 : C[m,e] = X[m,:] . W^T[e,:] + b[e]        (grid x = e-tile, y = m-tile)
// z==2: Vt[e,m] = Wv^T[e,:] . X[m,:] + bv[e]     (grid x = e-tile, y = m-tile,
//        roles of A/B swapped so the output is produced transposed directly;
//        bias indexed by row; ldc = MTOT). Same tile count: grid (8, 64, 3).
__global__ void __launch_bounds__(256, 2)
qkv_gemm(const __nv_bfloat16* __restrict__ Xh, const __nv_bfloat16* __restrict__ Xl,
         const __nv_bfloat16* __restrict__ Wqh, const __nv_bfloat16* __restrict__ Wql,
         const __nv_bfloat16* __restrict__ Wkh, const __nv_bfloat16* __restrict__ Wkl,
         const __nv_bfloat16* __restrict__ Wvh, const __nv_bfloat16* __restrict__ Wvl,
         const float* __restrict__ bq, const float* __restrict__ bk,
         const float* __restrict__ bv,
         __nv_bfloat16* __restrict__ Qh, __nv_bfloat16* __restrict__ Ql,
         __nv_bfloat16* __restrict__ Kh, __nv_bfloat16* __restrict__ Kl,
         __nv_bfloat16* __restrict__ Vth, __nv_bfloat16* __restrict__ Vtl)
{
    extern __shared__ __align__(128) char dsm[];
    const uint32_t base = s2u(dsm);
    const int tid = threadIdx.x, wid = tid >> 5, lid = tid & 31;
    const int wm = wid >> 2, wn = wid & 3;
    const int zz = blockIdx.z;

    float acc[4][4][4];
    #pragma unroll
    for (int i = 0; i < 4; i++)
        #pragma unroll
        for (int t = 0; t < 4; t++)
            #pragma unroll
            for (int j = 0; j < 4; j++) acc[i][t][j] = 0.0f;

    if (zz < 2) {
        const __nv_bfloat16* Bh = (zz == 0) ? Wqh : Wkh;
        const __nv_bfloat16* Bl = (zz == 0) ? Wql : Wkl;
        const float* bias       = (zz == 0) ? bq  : bk;
        __nv_bfloat16* Ch       = (zz == 0) ? Qh  : Kh;
        __nv_bfloat16* Cl       = (zz == 0) ? Ql  : Kl;
        const int m0 = blockIdx.y * 128, n0 = blockIdx.x * 128;

        gemm_mainloop(base, tid, wid, lid, wm, wn,
                      Xh + (long)m0 * D_, Xl + (long)m0 * D_, D_,
                      Bh + (long)n0 * D_, Bl + (long)n0 * D_, D_,
                      D_, acc);

        #pragma unroll
        for (int i = 0; i < 4; i++)
            #pragma unroll
            for (int nt = 0; nt < 4; nt++) {
                const int row = m0 + wm * 64 + i * 16 + (lid >> 2);
                const int col = n0 + wn * 32 + nt * 8 + 2 * (lid & 3);
                const float b0 = bias[col], b1 = bias[col + 1];
                float v0 = acc[i][nt][0] + b0, v1 = acc[i][nt][1] + b1;
                float v2 = acc[i][nt][2] + b0, v3 = acc[i][nt][3] + b1;
                const long o0 = (long)row * D_ + col;
                const long o1 = o0 + 8L * D_;
                __nv_bfloat16 h0 = __float2bfloat16(v0), h1 = __float2bfloat16(v1);
                __nv_bfloat16 h2 = __float2bfloat16(v2), h3 = __float2bfloat16(v3);
                __nv_bfloat16 l0 = __float2bfloat16(v0 - __bfloat162float(h0));
                __nv_bfloat16 l1 = __float2bfloat16(v1 - __bfloat162float(h1));
                __nv_bfloat16 l2 = __float2bfloat16(v2 - __bfloat162float(h2));
                __nv_bfloat16 l3 = __float2bfloat16(v3 - __bfloat162float(h3));
                __nv_bfloat162 ph0; ph0.x = h0; ph0.y = h1;
                __nv_bfloat162 ph1; ph1.x = h2; ph1.y = h3;
                __nv_bfloat162 pl0; pl0.x = l0; pl0.y = l1;
                __nv_bfloat162 pl1; pl1.x = l2; pl1.y = l3;
                *(__nv_bfloat162*)(Ch + o0) = ph0;
                *(__nv_bfloat162*)(Ch + o1) = ph1;
                *(__nv_bfloat162*)(Cl + o0) = pl0;
                *(__nv_bfloat162*)(Cl + o1) = pl1;
            }
    } else {
        // V^T slice: A = Wv^T (e-tiles on grid x), B = X (m-tiles on grid y)
        const int m0 = blockIdx.x * 128;     // e dimension (only 8 tiles)
        const int n0 = blockIdx.y * 128;     // m dimension (64 tiles)

        gemm_mainloop(base, tid, wid, lid, wm, wn,
                      Wvh + (long)m0 * D_, Wvl + (long)m0 * D_, D_,
                      Xh  + (long)n0 * D_, Xl  + (long)n0 * D_, D_,
                      D_, acc);

        #pragma unroll
        for (int i = 0; i < 4; i++)
            #pragma unroll
            for (int nt = 0; nt < 4; nt++) {
                const int row = m0 + wm * 64 + i * 16 + (lid >> 2);   // e
                const int col = n0 + wn * 32 + nt * 8 + 2 * (lid & 3); // m
                const float b0 = bv[row], b1 = bv[row + 8];
                float v0 = acc[i][nt][0] + b0, v1 = acc[i][nt][1] + b0;
                float v2 = acc[i][nt][2] + b1, v3 = acc[i][nt][3] + b1;
                const long o0 = (long)row * MTOT + col;
                const long o1 = o0 + 8L * MTOT;
                __nv_bfloat16 h0 = __float2bfloat16(v0), h1 = __float2bfloat16(v1);
                __nv_bfloat16 h2 = __float2bfloat16(v2), h3 = __float2bfloat16(v3);
                __nv_bfloat16 l0 = __float2bfloat16(v0 - __bfloat162float(h0));
                __nv_bfloat16 l1 = __float2bfloat16(v1 - __bfloat162float(h1));
                __nv_bfloat16 l2 = __float2bfloat16(v2 - __bfloat162float(h2));
                __nv_bfloat16 l3 = __float2bfloat16(v3 - __bfloat162float(h3));
                __nv_bfloat162 ph0; ph0.x = h0; ph0.y = h1;
                __nv_bfloat162 ph1; ph1.x = h2; ph1.y = h3;
                __nv_bfloat162 pl0; pl0.x = l0; pl0.y = l1;
                __nv_bfloat162 pl1; pl1.x = l2; pl1.y = l3;
                *(__nv_bfloat162*)(Vth + o0) = ph0;
                *(__nv_bfloat162*)(Vth + o1) = ph1;
                *(__nv_bfloat162*)(Vtl + o0) = pl0;
                *(__nv_bfloat162*)(Vtl + o1) = pl1;
            }
    }
}

// ================= prep kernels =================
__global__ void __launch_bounds__(256)
split_x_kernel(const float* __restrict__ X, __nv_bfloat16* __restrict__ Xh,
               __nv_bfloat16* __restrict__ Xl)
{
    const long i = ((long)blockIdx.x * 256 + threadIdx.x) * 4;
    float4 v = *(const float4*)(X + i);
    float vv[4] = { v.x, v.y, v.z, v.w };
    __nv_bfloat16 h[4], l[4];
    #pragma unroll
    for (int j = 0; j < 4; j++) {
        h[j] = __float2bfloat16(vv[j]);
        l[j] = __float2bfloat16(vv[j] - __bfloat162float(h[j]));
    }
    __nv_bfloat162 h01, h23, l01, l23;
    h01.x = h[0]; h01.y = h[1]; h23.x = h[2]; h23.y = h[3];
    l01.x = l[0]; l01.y = l[1]; l23.x = l[2]; l23.y = l[3];
    *(__nv_bfloat162*)(Xh + i)     = h01;
    *(__nv_bfloat162*)(Xh + i + 2) = h23;
    *(__nv_bfloat162*)(Xl + i)     = l01;
    *(__nv_bfloat162*)(Xl + i + 2) = l23;
}

// Transpose + split 1024x1024 weights: T[e][d] = W[d][e]
__global__ void __launch_bounds__(256)
transpose_split_kernel(const float* __restrict__ W0, const float* __restrict__ W1,
                       const float* __restrict__ W2,
                       __nv_bfloat16* __restrict__ T0h, __nv_bfloat16* __restrict__ T0l,
                       __nv_bfloat16* __restrict__ T1h, __nv_bfloat16* __restrict__ T1l,
                       __nv_bfloat16* __restrict__ T2h, __nv_bfloat16* __restrict__ T2l)
{
    __shared__ float t[32][33];
    const float* W = (blockIdx.z == 0) ? W0 : (blockIdx.z == 1) ? W1 : W2;
    __nv_bfloat16* Th = (blockIdx.z == 0) ? T0h : (blockIdx.z == 1) ? T1h : T2h;
    __nv_bfloat16* Tl = (blockIdx.z == 0) ? T0l : (blockIdx.z == 1) ? T1l : T2l;

    const int tx = threadIdx.x, ty = threadIdx.y;       // block 32x8
    const int e = blockIdx.x * 32 + tx;
    const int d0 = blockIdx.y * 32;
    #pragma unroll
    for (int i = ty; i < 32; i += 8)
        t[i][tx] = W[(long)(d0 + i) * D_ + e];
    __syncthreads();
    const int eo = blockIdx.x * 32;
    const int d = d0 + tx;
    #pragma unroll
    for (int i = ty; i < 32; i += 8) {
        float w = t[tx][i];
        __nv_bfloat16 h = __float2bfloat16(w);
        __nv_bfloat16 l = __float2bfloat16(w - __bfloat162float(h));
        Th[(long)(eo + i) * D_ + d] = h;
        Tl[(long)(eo + i) * D_ + d] = l;
    }
}

// Row softmax over S (length 2048), write split-bf16 P.
__global__ void __launch_bounds__(256)
softmax_split_kernel(const float* __restrict__ S, __nv_bfloat16* __restrict__ Ph,
                     __nv_bfloat16* __restrict__ Pl)
{
    const long row = blockIdx.x;
    const float* p = S + row * (long)N_;
    const int tid = threadIdx.x;

    float v[8];
    float mx = -1e30f;
    #pragma unroll
    for (int i = 0; i < 8; i++) { v[i] = p[tid + i * 256]; mx = fmaxf(mx, v[i]); }

    __shared__ float redm[8], reds[8];
    #pragma unroll
    for (int o = 16; o; o >>= 1) mx = fmaxf(mx, __shfl_xor_sync(0xffffffffu, mx, o));
    if ((tid & 31) == 0) redm[tid >> 5] = mx;
    __syncthreads();
    if (tid == 0) {
        float m = redm[0];
        #pragma unroll
        for (int i = 1; i < 8; i++) m = fmaxf(m, redm[i]);
        redm[0] = m;
    }
    __syncthreads();
    mx = redm[0];

    float s = 0.0f;
    #pragma unroll
    for (int i = 0; i < 8; i++) { v[i] = __expf(v[i] - mx); s += v[i]; }
    #pragma unroll
    for (int o = 16; o; o >>= 1) s += __shfl_xor_sync(0xffffffffu, s, o);
    if ((tid & 31) == 0) reds[tid >> 5] = s;
    __syncthreads();
    if (tid == 0) {
        float m = 0.0f;
        #pragma unroll
        for (int i = 0; i < 8; i++) m += reds[i];
        reds[0] = m;
    }
    __syncthreads();
    const float inv = 1.0f / reds[0];

    #pragma unroll
    for (int i = 0; i < 8; i++) {
        float w = v[i] * inv;
        __nv_bfloat16 h = __float2bfloat16(w);
        __nv_bfloat16 l = __float2bfloat16(w - __bfloat162float(h));
        Ph[row * (long)N_ + tid + i * 256] = h;
        Pl[row * (long)N_ + tid + i * 256] = l;
    }
}

// ================= host glue =================
extern "C" void kernel_launch(void* const* d_in, const int* in_sizes, int n_in,
                              void* d_out, int out_size)
{
    const float* X  = (const float*)d_in[0];
    const float* Wq = (const float*)d_in[1];
    const float* bq = (const float*)d_in[2];
    const float* Wk = (const float*)d_in[3];
    const float* bk = (const float*)d_in[4];
    const float* Wv = (const float*)d_in[5];
    const float* bv = (const float*)d_in[6];
    float* out = (float*)d_out;

    __nv_bfloat16 *Xh, *Xl, *Qh, *Ql, *Kh, *Kl, *Vth, *Vtl;
    __nv_bfloat16 *Wqth, *Wqtl, *Wkth, *Wktl, *Wvth, *Wvtl, *Ph, *Pl;
    float* S;
    cudaGetSymbolAddress((void**)&Xh, g_Xh);   cudaGetSymbolAddress((void**)&Xl, g_Xl);
    cudaGetSymbolAddress((void**)&Qh, g_Qh);   cudaGetSymbolAddress((void**)&Ql, g_Ql);
    cudaGetSymbolAddress((void**)&Kh, g_Kh);   cudaGetSymbolAddress((void**)&Kl, g_Kl);
    cudaGetSymbolAddress((void**)&Vth, g_Vth); cudaGetSymbolAddress((void**)&Vtl, g_Vtl);
    cudaGetSymbolAddress((void**)&Wqth, g_Wqth); cudaGetSymbolAddress((void**)&Wqtl, g_Wqtl);
    cudaGetSymbolAddress((void**)&Wkth, g_Wkth); cudaGetSymbolAddress((void**)&Wktl, g_Wktl);
    cudaGetSymbolAddress((void**)&Wvth, g_Wvth); cudaGetSymbolAddress((void**)&Wvtl, g_Wvtl);
    cudaGetSymbolAddress((void**)&Ph, g_Ph);   cudaGetSymbolAddress((void**)&Pl, g_Pl);
    cudaGetSymbolAddress((void**)&S, g_S);

    cudaFuncSetAttribute((const void*)qkv_gemm,      cudaFuncAttributeMaxDynamicSharedMemorySize, (int)SMEM_BYTES);
    cudaFuncSetAttribute((const void*)tc_gemm<0, 0>, cudaFuncAttributeMaxDynamicSharedMemorySize, (int)SMEM_BYTES);

    dim3 blk(256);

    // 0) split X, transpose+split weights
    split_x_kernel<<<(MTOT * D_) / 1024, 256>>>(X, Xh, Xl);
    transpose_split_kernel<<<dim3(32, 32, 3), dim3(32, 8)>>>(
        Wq, Wk, Wv, Wqth, Wqtl, Wkth, Wktl, Wvth, Wvtl);

    // 1) fused QKV projection: one launch; z=2 emits V^T directly (no transpose)
    qkv_gemm<<<dim3(8, 64, 3), blk, SMEM_BYTES>>>(
        Xh, Xl, Wqth, Wqtl, Wkth, Wktl, Wvth, Wvtl,
        bq, bk, bv, Qh, Ql, Kh, Kl, Vth, Vtl);

    // 2) S = Q K^T per batch (fp32)
    tc_gemm<0, 0><<<dim3(16, 16, B_), blk, SMEM_BYTES>>>(
        Qh, Ql, D_, (long)N_ * D_, Kh, Kl, D_, (long)N_ * D_,
        S, nullptr, nullptr, N_, (long)N_ * N_, nullptr, D_);

    // 3) softmax + split P
    softmax_split_kernel<<<B_ * N_, 256>>>(S, Ph, Pl);

    // 4) out = P V per batch (NT against V^T, fp32 out)
    tc_gemm<0, 0><<<dim3(8, 16, B_), blk, SMEM_BYTES>>>(
        Ph, Pl, N_, (long)N_ * N_, Vth, Vtl, MTOT, (long)N_,
        out, nullptr, nullptr, D_, (long)N_ * D_, nullptr, N_);
}

// round 16
// speedup vs baseline: 1.0530x; 1.0055x over previous
#include <cuda_runtime.h>
#include <cuda_bf16.h>
#include <cstdint>
#include <math.h>

// Problem constants
constexpr int B_   = 4;
constexpr int N_   = 2048;
constexpr int D_   = 1024;
constexpr int MTOT = B_ * N_;  // 8192

// ---------------- scratch (static __device__, allocation-free) ----------------
__device__ __align__(1024) __nv_bfloat16 g_Xh[(size_t)MTOT * D_];
__device__ __align__(1024) __nv_bfloat16 g_Xl[(size_t)MTOT * D_];
__device__ __align__(1024) __nv_bfloat16 g_Qh[(size_t)MTOT * D_];
__device__ __align__(1024) __nv_bfloat16 g_Ql[(size_t)MTOT * D_];
__device__ __align__(1024) __nv_bfloat16 g_Kh[(size_t)MTOT * D_];
__device__ __align__(1024) __nv_bfloat16 g_Kl[(size_t)MTOT * D_];
__device__ __align__(1024) __nv_bfloat16 g_Vth[(size_t)D_ * MTOT];   // V^T [e][m]
__device__ __align__(1024) __nv_bfloat16 g_Vtl[(size_t)D_ * MTOT];
__device__ __align__(1024) __nv_bfloat16 g_Wqth[(size_t)D_ * D_];    // W^T [e][d]
__device__ __align__(1024) __nv_bfloat16 g_Wqtl[(size_t)D_ * D_];
__device__ __align__(1024) __nv_bfloat16 g_Wkth[(size_t)D_ * D_];
__device__ __align__(1024) __nv_bfloat16 g_Wktl[(size_t)D_ * D_];
__device__ __align__(1024) __nv_bfloat16 g_Wvth[(size_t)D_ * D_];
__device__ __align__(1024) __nv_bfloat16 g_Wvtl[(size_t)D_ * D_];
__device__ __align__(1024) float         g_S [(size_t)B_ * N_ * N_]; // 64 MB
__device__ __align__(1024) __nv_bfloat16 g_Ph[(size_t)B_ * N_ * N_];
__device__ __align__(1024) __nv_bfloat16 g_Pl[(size_t)B_ * N_ * N_];

// ---------------- helpers (plain sm_80-level PTX only; no 'a' features) -------
__device__ __forceinline__ uint32_t s2u(const void* p) {
    uint32_t a;
    asm("{ .reg .u64 t; cvta.to.shared.u64 t, %1; cvt.u32.u64 %0, t; }" : "=r"(a) : "l"(p));
    return a;
}
__device__ __forceinline__ void cpasync16(uint32_t dst, const void* src) {
    asm volatile("cp.async.cg.shared.global [%0], [%1], 16;" :: "r"(dst), "l"(src));
}
__device__ __forceinline__ void ldm4(uint32_t (&r)[4], uint32_t addr) {
    asm volatile("ldmatrix.sync.aligned.m8n8.x4.shared.b16 {%0,%1,%2,%3}, [%4];"
                 : "=r"(r[0]), "=r"(r[1]), "=r"(r[2]), "=r"(r[3]) : "r"(addr));
}
__device__ __forceinline__ void mma16816(float (&c)[4], const uint32_t* a,
                                         uint32_t b0, uint32_t b1) {
    asm volatile(
        "mma.sync.aligned.m16n8k16.row.col.f32.bf16.bf16.f32 "
        "{%0,%1,%2,%3}, {%4,%5,%6,%7}, {%8,%9}, {%0,%1,%2,%3};"
        : "+f"(c[0]), "+f"(c[1]), "+f"(c[2]), "+f"(c[3])
        : "r"(a[0]), "r"(a[1]), "r"(a[2]), "r"(a[3]), "r"(b0), "r"(b1));
}
// Tile row = 32 bf16 = 64B; swizzle 16B chunk index within row for conflict-free ldmatrix
__device__ __forceinline__ uint32_t swoff(int row, int kb) {
    return (uint32_t)(row * 64 + ((kb ^ ((row >> 1) & 3)) << 4));
}

constexpr int TILE_BYTES = 128 * 32 * 2;     // 8 KB: 128 rows x 32 bf16
constexpr int STAGES     = 3;
constexpr size_t SMEM_BYTES = (size_t)STAGES * 4 * TILE_BYTES;  // 96 KB -> 2 CTAs/SM

// ---------------- shared GEMM mainloop ----------------
// Computes the 128x128 split-bf16 NT GEMM for one block tile into acc.
// Inner k16 step is software-pipelined: hi-plane LDSMs -> hh MMAs (tensor busy)
// while the lo-plane LDSMs issue on MIO behind them -> hl + lh MMAs. ldm4 is
// volatile so this source order IS the issue order; it overlaps MIO with the
// tensor pipe instead of serializing 12 LDSMs before the first MMA.
__device__ __forceinline__ void gemm_mainloop(
    uint32_t base, int tid, int wid, int lid, int wm, int wn,
    const __nv_bfloat16* aH, const __nv_bfloat16* aL, int lda,
    const __nv_bfloat16* bH, const __nv_bfloat16* bL, int ldb,
    int Kd, float (&acc)[4][4][4])
{
    const __nv_bfloat16* srcs[4] = { aH, aL, bH, bL };
    const int ldsv[4] = { lda, lda, ldb, ldb };

    auto load_chunk = [&](int chunk, int stage) {
        #pragma unroll
        for (int p = 0; p < 4; p++) {
            const __nv_bfloat16* s = srcs[p] + chunk * 32;
            const int ld = ldsv[p];
            const uint32_t tb = base + (uint32_t)((stage * 4 + p) * TILE_BYTES);
            #pragma unroll
            for (int i = 0; i < 2; i++) {
                int o = i * 256 + tid;          // 512 chunks of 16B
                int r = o >> 2, kb = o & 3;
                cpasync16(tb + swoff(r, kb), s + (long)r * ld + kb * 8);
            }
        }
        asm volatile("cp.async.commit_group;" ::: "memory");
    };

    const int nk = Kd / 32;
    load_chunk(0, 0); load_chunk(1, 1);

    const int rA  = (lid & 7) + ((lid >> 3) & 1) * 8;  // ldmatrix row-in-16
    const int kbh = (lid >> 4) & 1;                    // ldmatrix k-half

    int stage = 0;      // stage of chunk k
    int pstage = 2;     // stage of chunk k+2 == stage of chunk k-1

    for (int k = 0; k < nk; k++) {
        if (k + 1 < nk) asm volatile("cp.async.wait_group 1;" ::: "memory");
        else            asm volatile("cp.async.wait_group 0;" ::: "memory");
        __syncthreads();
        // Barrier proves chunk k-1's compute finished everywhere; its stage
        // equals (k+2)%3 — free to refill now. ONE barrier per chunk.
        if (k + 2 < nk) load_chunk(k + 2, pstage);

        const uint32_t sb  = base + (uint32_t)(stage * 4 * TILE_BYTES);
        const uint32_t tAh = sb;
        const uint32_t tAl = sb + TILE_BYTES;
        const uint32_t tBh = sb + 2 * TILE_BYTES;
        const uint32_t tBl = sb + 3 * TILE_BYTES;

        #pragma unroll
        for (int p = 0; p < 2; p++) {            // two k16 steps per 32-chunk
            // All our fragment rows differ by multiples of 16, so the swizzle
            // XOR term (kb ^ (row>>1)&3) is uniform across them.
            const uint32_t kxor = (uint32_t)(((2 * p + kbh) ^ ((rA >> 1) & 3)) << 4);
            uint32_t fAh[4][4], fAl[4][4], fBh[2][4], fBl[2][4];

            // --- stage 1: hi-plane LDSMs only (6) ---
            #pragma unroll
            for (int i = 0; i < 4; i++) {
                const uint32_t rb = (uint32_t)((wm * 64 + i * 16 + rA) * 64);
                ldm4(fAh[i], tAh + rb + kxor);
            }
            #pragma unroll
            for (int q = 0; q < 2; q++) {
                const uint32_t rb = (uint32_t)((wn * 32 + q * 16 + rA) * 64);
                ldm4(fBh[q], tBh + rb + kxor);
            }
            // --- pass 1: hh (16 MMAs) — tensor pipe fills while we prepare lo ---
            #pragma unroll
            for (int i = 0; i < 4; i++)
                #pragma unroll
                for (int nt = 0; nt < 4; nt++) {
                    const int q = nt >> 1, sx = nt & 1;
                    mma16816(acc[i][nt], fAh[i], fBh[q][sx], fBh[q][sx + 2]);
                }
            // --- stage 2: lo-plane LDSMs issue on MIO under the hh MMA drain ---
            #pragma unroll
            for (int i = 0; i < 4; i++) {
                const uint32_t rb = (uint32_t)((wm * 64 + i * 16 + rA) * 64);
                ldm4(fAl[i], tAl + rb + kxor);
            }
            #pragma unroll
            for (int q = 0; q < 2; q++) {
                const uint32_t rb = (uint32_t)((wn * 32 + q * 16 + rA) * 64);
                ldm4(fBl[q], tBl + rb + kxor);
            }
            // --- pass 2: hl ---
            #pragma unroll
            for (int i = 0; i < 4; i++)
                #pragma unroll
                for (int nt = 0; nt < 4; nt++) {
                    const int q = nt >> 1, sx = nt & 1;
                    mma16816(acc[i][nt], fAh[i], fBl[q][sx], fBl[q][sx + 2]);
                }
            // --- pass 3: lh ---
            #pragma unroll
            for (int i = 0; i < 4; i++)
                #pragma unroll
                for (int nt = 0; nt < 4; nt++) {
                    const int q = nt >> 1, sx = nt & 1;
                    mma16816(acc[i][nt], fAl[i], fBh[q][sx], fBh[q][sx + 2]);
                }
        }
        stage  = (stage  == STAGES - 1) ? 0 : stage + 1;
        pstage = (pstage == STAGES - 1) ? 0 : pstage + 1;
    }
}

// ================= generic split-bf16 GEMM (S = QK^T, out = PV) =================
// OUTMODE: 0 = fp32 C, 1 = split hi/lo bf16 C. BIASMODE: 0 none, 1 by col.
template<int OUTMODE, int BIASMODE>
__global__ void __launch_bounds__(256, 2)
tc_gemm(const __nv_bfloat16* __restrict__ Ah, const __nv_bfloat16* __restrict__ Al,
        int lda, long sA,
        const __nv_bfloat16* __restrict__ Bh, const __nv_bfloat16* __restrict__ Bl,
        int ldb, long sB,
        float* __restrict__ Cf, __nv_bfloat16* __restrict__ Ch, __nv_bfloat16* __restrict__ Cl,
        int ldc, long sC, const float* __restrict__ bias, int Kd)
{
    extern __shared__ __align__(128) char dsm[];
    const uint32_t base = s2u(dsm);
    const int tid = threadIdx.x, wid = tid >> 5, lid = tid & 31;
    const int wm = wid >> 2, wn = wid & 3;
    const int m0 = blockIdx.y * 128, n0 = blockIdx.x * 128;
    const long z = blockIdx.z;

    float acc[4][4][4];
    #pragma unroll
    for (int i = 0; i < 4; i++)
        #pragma unroll
        for (int t = 0; t < 4; t++)
            #pragma unroll
            for (int j = 0; j < 4; j++) acc[i][t][j] = 0.0f;

    gemm_mainloop(base, tid, wid, lid, wm, wn,
                  Ah + z * sA + (long)m0 * lda, Al + z * sA + (long)m0 * lda, lda,
                  Bh + z * sB + (long)n0 * ldb, Bl + z * sB + (long)n0 * ldb, ldb,
                  Kd, acc);

    #pragma unroll
    for (int i = 0; i < 4; i++)
        #pragma unroll
        for (int nt = 0; nt < 4; nt++) {
            const int row = m0 + wm * 64 + i * 16 + (lid >> 2);
            const int col = n0 + wn * 32 + nt * 8 + 2 * (lid & 3);
            float v0 = acc[i][nt][0], v1 = acc[i][nt][1];
            float v2 = acc[i][nt][2], v3 = acc[i][nt][3];
            if (BIASMODE == 1) {
                const float b0 = bias[col], b1 = bias[col + 1];
                v0 += b0; v1 += b1; v2 += b0; v3 += b1;
            }
            const long o0 = (long)row * ldc + col + z * sC;
            const long o1 = o0 + 8L * ldc;
            if (OUTMODE == 0) {
                *(float2*)(Cf + o0) = make_float2(v0, v1);
                *(float2*)(Cf + o1) = make_float2(v2, v3);
            } else {
                __nv_bfloat16 h0 = __float2bfloat16(v0), h1 = __float2bfloat16(v1);
                __nv_bfloat16 h2 = __float2bfloat16(v2), h3 = __float2bfloat16(v3);
                __nv_bfloat16 l0 = __float2bfloat16(v0 - __bfloat162float(h0));
                __nv_bfloat16 l1 = __float2bfloat16(v1 - __bfloat162float(h1));
                __nv_bfloat16 l2 = __float2bfloat16(v2 - __bfloat162float(h2));
                __nv_bfloat16 l3 = __float2bfloat16(v3 - __bfloat162float(h3));
                __nv_bfloat162 ph0; ph0.x = h0; ph0.y = h1;
                __nv_bfloat162 ph1; ph1.x = h2; ph1.y = h3;
                __nv_bfloat162 pl0; pl0.x = l0; pl0.y = l1;
                __nv_bfloat162 pl1; pl1.x = l2; pl1.y = l3;
                *(__nv_bfloat162*)(Ch + o0) = ph0;
                *(__nv_bfloat162*)(Ch + o1) = ph1;
                *(__nv_bfloat162*)(Cl + o0) = pl0;
                *(__nv_bfloat162*)(Cl + o1) = pl1;
            }
        }
}

// ===== fused QKV projection: one launch; z=0 -> Q, z=1 -> K, z=2 -> V^T =======
// z<2 : C[m,e] = X[m,:] . W^T[e,:] + b[e]        (grid x = e-tile, y = m-tile)
// z==2: Vt[e,m] = Wv^T[e,:] . X[m,:] + bv[e]     (roles of A/B swapped so the
//        output is produced transposed directly; bias by row; ldc = MTOT).
__global__ void __launch_bounds__(256, 2)
qkv_gemm(const __nv_bfloat16* __restrict__ Xh, const __nv_bfloat16* __restrict__ Xl,
         const __nv_bfloat16* __restrict__ Wqh, const __nv_bfloat16* __restrict__ Wql,
         const __nv_bfloat16* __restrict__ Wkh, const __nv_bfloat16* __restrict__ Wkl,
         const __nv_bfloat16* __restrict__ Wvh, const __nv_bfloat16* __restrict__ Wvl,
         const float* __restrict__ bq, const float* __restrict__ bk,
         const float* __restrict__ bv,
         __nv_bfloat16* __restrict__ Qh, __nv_bfloat16* __restrict__ Ql,
         __nv_bfloat16* __restrict__ Kh, __nv_bfloat16* __restrict__ Kl,
         __nv_bfloat16* __restrict__ Vth, __nv_bfloat16* __restrict__ Vtl)
{
    extern __shared__ __align__(128) char dsm[];
    const uint32_t base = s2u(dsm);
    const int tid = threadIdx.x, wid = tid >> 5, lid = tid & 31;
    const int wm = wid >> 2, wn = wid & 3;
    const int zz = blockIdx.z;

    float acc[4][4][4];
    #pragma unroll
    for (int i = 0; i < 4; i++)
        #pragma unroll
        for (int t = 0; t < 4; t++)
            #pragma unroll
            for (int j = 0; j < 4; j++) acc[i][t][j] = 0.0f;

    if (zz < 2) {
        const __nv_bfloat16* Bh = (zz == 0) ? Wqh : Wkh;
        const __nv_bfloat16* Bl = (zz == 0) ? Wql : Wkl;
        const float* bias       = (zz == 0) ? bq  : bk;
        __nv_bfloat16* Ch       = (zz == 0) ? Qh  : Kh;
        __nv_bfloat16* Cl       = (zz == 0) ? Ql  : Kl;
        const int m0 = blockIdx.y * 128, n0 = blockIdx.x * 128;

        gemm_mainloop(base, tid, wid, lid, wm, wn,
                      Xh + (long)m0 * D_, Xl + (long)m0 * D_, D_,
                      Bh + (long)n0 * D_, Bl + (long)n0 * D_, D_,
                      D_, acc);

        #pragma unroll
        for (int i = 0; i < 4; i++)
            #pragma unroll
            for (int nt = 0; nt < 4; nt++) {
                const int row = m0 + wm * 64 + i * 16 + (lid >> 2);
                const int col = n0 + wn * 32 + nt * 8 + 2 * (lid & 3);
                const float b0 = bias[col], b1 = bias[col + 1];
                float v0 = acc[i][nt][0] + b0, v1 = acc[i][nt][1] + b1;
                float v2 = acc[i][nt][2] + b0, v3 = acc[i][nt][3] + b1;
                const long o0 = (long)row * D_ + col;
                const long o1 = o0 + 8L * D_;
                __nv_bfloat16 h0 = __float2bfloat16(v0), h1 = __float2bfloat16(v1);
                __nv_bfloat16 h2 = __float2bfloat16(v2), h3 = __float2bfloat16(v3);
                __nv_bfloat16 l0 = __float2bfloat16(v0 - __bfloat162float(h0));
                __nv_bfloat16 l1 = __float2bfloat16(v1 - __bfloat162float(h1));
                __nv_bfloat16 l2 = __float2bfloat16(v2 - __bfloat162float(h2));
                __nv_bfloat16 l3 = __float2bfloat16(v3 - __bfloat162float(h3));
                __nv_bfloat162 ph0; ph0.x = h0; ph0.y = h1;
                __nv_bfloat162 ph1; ph1.x = h2; ph1.y = h3;
                __nv_bfloat162 pl0; pl0.x = l0; pl0.y = l1;
                __nv_bfloat162 pl1; pl1.x = l2; pl1.y = l3;
                *(__nv_bfloat162*)(Ch + o0) = ph0;
                *(__nv_bfloat162*)(Ch + o1) = ph1;
                *(__nv_bfloat162*)(Cl + o0) = pl0;
                *(__nv_bfloat162*)(Cl + o1) = pl1;
            }
    } else {
        // V^T slice: A = Wv^T (e-tiles on grid x), B = X (m-tiles on grid y)
        const int m0 = blockIdx.x * 128;     // e dimension (only 8 tiles)
        const int n0 = blockIdx.y * 128;     // m dimension (64 tiles)

        gemm_mainloop(base, tid, wid, lid, wm, wn,
                      Wvh + (long)m0 * D_, Wvl + (long)m0 * D_, D_,
                      Xh  + (long)n0 * D_, Xl  + (long)n0 * D_, D_,
                      D_, acc);

        #pragma unroll
        for (int i = 0; i < 4; i++)
            #pragma unroll
            for (int nt = 0; nt < 4; nt++) {
                const int row = m0 + wm * 64 + i * 16 + (lid >> 2);   // e
                const int col = n0 + wn * 32 + nt * 8 + 2 * (lid & 3); // m
                const float b0 = bv[row], b1 = bv[row + 8];
                float v0 = acc[i][nt][0] + b0, v1 = acc[i][nt][1] + b0;
                float v2 = acc[i][nt][2] + b1, v3 = acc[i][nt][3] + b1;
                const long o0 = (long)row * MTOT + col;
                const long o1 = o0 + 8L * MTOT;
                __nv_bfloat16 h0 = __float2bfloat16(v0), h1 = __float2bfloat16(v1);
                __nv_bfloat16 h2 = __float2bfloat16(v2), h3 = __float2bfloat16(v3);
                __nv_bfloat16 l0 = __float2bfloat16(v0 - __bfloat162float(h0));
                __nv_bfloat16 l1 = __float2bfloat16(v1 - __bfloat162float(h1));
                __nv_bfloat16 l2 = __float2bfloat16(v2 - __bfloat162float(h2));
                __nv_bfloat16 l3 = __float2bfloat16(v3 - __bfloat162float(h3));
                __nv_bfloat162 ph0; ph0.x = h0; ph0.y = h1;
                __nv_bfloat162 ph1; ph1.x = h2; ph1.y = h3;
                __nv_bfloat162 pl0; pl0.x = l0; pl0.y = l1;
                __nv_bfloat162 pl1; pl1.x = l2; pl1.y = l3;
                *(__nv_bfloat162*)(Vth + o0) = ph0;
                *(__nv_bfloat162*)(Vth + o1) = ph1;
                *(__nv_bfloat162*)(Vtl + o0) = pl0;
                *(__nv_bfloat162*)(Vtl + o1) = pl1;
            }
    }
}

// ================= prep kernels =================
__global__ void __launch_bounds__(256)
split_x_kernel(const float* __restrict__ X, __nv_bfloat16* __restrict__ Xh,
               __nv_bfloat16* __restrict__ Xl)
{
    const long i = ((long)blockIdx.x * 256 + threadIdx.x) * 4;
    float4 v = *(const float4*)(X + i);
    float vv[4] = { v.x, v.y, v.z, v.w };
    __nv_bfloat16 h[4], l[4];
    #pragma unroll
    for (int j = 0; j < 4; j++) {
        h[j] = __float2bfloat16(vv[j]);
        l[j] = __float2bfloat16(vv[j] - __bfloat162float(h[j]));
    }
    __nv_bfloat162 h01, h23, l01, l23;
    h01.x = h[0]; h01.y = h[1]; h23.x = h[2]; h23.y = h[3];
    l01.x = l[0]; l01.y = l[1]; l23.x = l[2]; l23.y = l[3];
    *(__nv_bfloat162*)(Xh + i)     = h01;
    *(__nv_bfloat162*)(Xh + i + 2) = h23;
    *(__nv_bfloat162*)(Xl + i)     = l01;
    *(__nv_bfloat162*)(Xl + i + 2) = l23;
}

// Transpose + split 1024x1024 weights: T[e][d] = W[d][e]
__global__ void __launch_bounds__(256)
transpose_split_kernel(const float* __restrict__ W0, const float* __restrict__ W1,
                       const float* __restrict__ W2,
                       __nv_bfloat16* __restrict__ T0h, __nv_bfloat16* __restrict__ T0l,
                       __nv_bfloat16* __restrict__ T1h, __nv_bfloat16* __restrict__ T1l,
                       __nv_bfloat16* __restrict__ T2h, __nv_bfloat16* __restrict__ T2l)
{
    __shared__ float t[32][33];
    const float* W = (blockIdx.z == 0) ? W0 : (blockIdx.z == 1) ? W1 : W2;
    __nv_bfloat16* Th = (blockIdx.z == 0) ? T0h : (blockIdx.z == 1) ? T1h : T2h;
    __nv_bfloat16* Tl = (blockIdx.z == 0) ? T0l : (blockIdx.z == 1) ? T1l : T2l;

    const int tx = threadIdx.x, ty = threadIdx.y;       // block 32x8
    const int e = blockIdx.x * 32 + tx;
    const int d0 = blockIdx.y * 32;
    #pragma unroll
    for (int i = ty; i < 32; i += 8)
        t[i][tx] = W[(long)(d0 + i) * D_ + e];
    __syncthreads();
    const int eo = blockIdx.x * 32;
    const int d = d0 + tx;
    #pragma unroll
    for (int i = ty; i < 32; i += 8) {
        float w = t[tx][i];
        __nv_bfloat16 h = __float2bfloat16(w);
        __nv_bfloat16 l = __float2bfloat16(w - __bfloat162float(h));
        Th[(long)(eo + i) * D_ + d] = h;
        Tl[(long)(eo + i) * D_ + d] = l;
    }
}

// Row softmax over S (length 2048), write split-bf16 P.
__global__ void __launch_bounds__(256)
softmax_split_kernel(const float* __restrict__ S, __nv_bfloat16* __restrict__ Ph,
                     __nv_bfloat16* __restrict__ Pl)
{
    const long row = blockIdx.x;
    const float* p = S + row * (long)N_;
    const int tid = threadIdx.x;

    float v[8];
    float mx = -1e30f;
    #pragma unroll
    for (int i = 0; i < 8; i++) { v[i] = p[tid + i * 256]; mx = fmaxf(mx, v[i]); }

    __shared__ float redm[8], reds[8];
    #pragma unroll
    for (int o = 16; o; o >>= 1) mx = fmaxf(mx, __shfl_xor_sync(0xffffffffu, mx, o));
    if ((tid & 31) == 0) redm[tid >> 5] = mx;
    __syncthreads();
    if (tid == 0) {
        float m = redm[0];
        #pragma unroll
        for (int i = 1; i < 8; i++) m = fmaxf(m, redm[i]);
        redm[0] = m;
    }
    __syncthreads();
    mx = redm[0];

    float s = 0.0f;
    #pragma unroll
    for (int i = 0; i < 8; i++) { v[i] = __expf(v[i] - mx); s += v[i]; }
    #pragma unroll
    for (int o = 16; o; o >>= 1) s += __shfl_xor_sync(0xffffffffu, s, o);
    if ((tid & 31) == 0) reds[tid >> 5] = s;
    __syncthreads();
    if (tid == 0) {
        float m = 0.0f;
        #pragma unroll
        for (int i = 0; i < 8; i++) m += reds[i];
        reds[0] = m;
    }
    __syncthreads();
    const float inv = 1.0f / reds[0];

    #pragma unroll
    for (int i = 0; i < 8; i++) {
        float w = v[i] * inv;
        __nv_bfloat16 h = __float2bfloat16(w);
        __nv_bfloat16 l = __float2bfloat16(w - __bfloat162float(h));
        Ph[row * (long)N_ + tid + i * 256] = h;
        Pl[row * (long)N_ + tid + i * 256] = l;
    }
}

// ================= host glue =================
extern "C" void kernel_launch(void* const* d_in, const int* in_sizes, int n_in,
                              void* d_out, int out_size)
{
    const float* X  = (const float*)d_in[0];
    const float* Wq = (const float*)d_in[1];
    const float* bq = (const float*)d_in[2];
    const float* Wk = (const float*)d_in[3];
    const float* bk = (const float*)d_in[4];
    const float* Wv = (const float*)d_in[5];
    const float* bv = (const float*)d_in[6];
    float* out = (float*)d_out;

    __nv_bfloat16 *Xh, *Xl, *Qh, *Ql, *Kh, *Kl, *Vth, *Vtl;
    __nv_bfloat16 *Wqth, *Wqtl, *Wkth, *Wktl, *Wvth, *Wvtl, *Ph, *Pl;
    float* S;
    cudaGetSymbolAddress((void**)&Xh, g_Xh);   cudaGetSymbolAddress((void**)&Xl, g_Xl);
    cudaGetSymbolAddress((void**)&Qh, g_Qh);   cudaGetSymbolAddress((void**)&Ql, g_Ql);
    cudaGetSymbolAddress((void**)&Kh, g_Kh);   cudaGetSymbolAddress((void**)&Kl, g_Kl);
    cudaGetSymbolAddress((void**)&Vth, g_Vth); cudaGetSymbolAddress((void**)&Vtl, g_Vtl);
    cudaGetSymbolAddress((void**)&Wqth, g_Wqth); cudaGetSymbolAddress((void**)&Wqtl, g_Wqtl);
    cudaGetSymbolAddress((void**)&Wkth, g_Wkth); cudaGetSymbolAddress((void**)&Wktl, g_Wktl);
    cudaGetSymbolAddress((void**)&Wvth, g_Wvth); cudaGetSymbolAddress((void**)&Wvtl, g_Wvtl);
    cudaGetSymbolAddress((void**)&Ph, g_Ph);   cudaGetSymbolAddress((void**)&Pl, g_Pl);
    cudaGetSymbolAddress((void**)&S, g_S);

    cudaFuncSetAttribute((const void*)qkv_gemm,      cudaFuncAttributeMaxDynamicSharedMemorySize, (int)SMEM_BYTES);
    cudaFuncSetAttribute((const void*)tc_gemm<0, 0>, cudaFuncAttributeMaxDynamicSharedMemorySize, (int)SMEM_BYTES);

    dim3 blk(256);

    // 0) split X, transpose+split weights
    split_x_kernel<<<(MTOT * D_) / 1024, 256>>>(X, Xh, Xl);
    transpose_split_kernel<<<dim3(32, 32, 3), dim3(32, 8)>>>(
        Wq, Wk, Wv, Wqth, Wqtl, Wkth, Wktl, Wvth, Wvtl);

    // 1) fused QKV projection: one launch; z=2 emits V^T directly (no transpose)
    qkv_gemm<<<dim3(8, 64, 3), blk, SMEM_BYTES>>>(
        Xh, Xl, Wqth, Wqtl, Wkth, Wktl, Wvth, Wvtl,
        bq, bk, bv, Qh, Ql, Kh, Kl, Vth, Vtl);

    // 2) S = Q K^T per batch (fp32)
    tc_gemm<0, 0><<<dim3(16, 16, B_), blk, SMEM_BYTES>>>(
        Qh, Ql, D_, (long)N_ * D_, Kh, Kl, D_, (long)N_ * D_,
        S, nullptr, nullptr, N_, (long)N_ * N_, nullptr, D_);

    // 3) softmax + split P
    softmax_split_kernel<<<B_ * N_, 256>>>(S, Ph, Pl);

    // 4) out = P V per batch (NT against V^T, fp32 out)
    tc_gemm<0, 0><<<dim3(8, 16, B_), blk, SMEM_BYTES>>>(
        Ph, Pl, N_, (long)N_ * N_, Vth, Vtl, MTOT, (long)N_,
        out, nullptr, nullptr, D_, (long)N_ * D_, nullptr, N_);
}

// round 17
// speedup vs baseline: 1.0567x; 1.0035x over previous
#include <cuda_runtime.h>
#include <cuda_bf16.h>
#include <cstdint>
#include <math.h>

// Problem constants
constexpr int B_   = 4;
constexpr int N_   = 2048;
constexpr int D_   = 1024;
constexpr int MTOT = B_ * N_;  // 8192

// ---------------- scratch (static __device__, allocation-free) ----------------
__device__ __align__(1024) __nv_bfloat16 g_Xh[(size_t)MTOT * D_];
__device__ __align__(1024) __nv_bfloat16 g_Xl[(size_t)MTOT * D_];
__device__ __align__(1024) __nv_bfloat16 g_Qh[(size_t)MTOT * D_];
__device__ __align__(1024) __nv_bfloat16 g_Ql[(size_t)MTOT * D_];
__device__ __align__(1024) __nv_bfloat16 g_Kh[(size_t)MTOT * D_];
__device__ __align__(1024) __nv_bfloat16 g_Kl[(size_t)MTOT * D_];
__device__ __align__(1024) __nv_bfloat16 g_Vth[(size_t)D_ * MTOT];   // V^T [e][m]
__device__ __align__(1024) __nv_bfloat16 g_Vtl[(size_t)D_ * MTOT];
__device__ __align__(1024) __nv_bfloat16 g_Wqth[(size_t)D_ * D_];    // W^T [e][d]
__device__ __align__(1024) __nv_bfloat16 g_Wqtl[(size_t)D_ * D_];
__device__ __align__(1024) __nv_bfloat16 g_Wkth[(size_t)D_ * D_];
__device__ __align__(1024) __nv_bfloat16 g_Wktl[(size_t)D_ * D_];
__device__ __align__(1024) __nv_bfloat16 g_Wvth[(size_t)D_ * D_];
__device__ __align__(1024) __nv_bfloat16 g_Wvtl[(size_t)D_ * D_];
__device__ __align__(1024) float         g_S [(size_t)B_ * N_ * N_]; // 64 MB
__device__ __align__(1024) __nv_bfloat16 g_Ph[(size_t)B_ * N_ * N_];
__device__ __align__(1024) __nv_bfloat16 g_Pl[(size_t)B_ * N_ * N_];

// ---------------- helpers (plain sm_80-level PTX only; no 'a' features) -------
__device__ __forceinline__ uint32_t s2u(const void* p) {
    uint32_t a;
    asm("{ .reg .u64 t; cvta.to.shared.u64 t, %1; cvt.u32.u64 %0, t; }" : "=r"(a) : "l"(p));
    return a;
}
__device__ __forceinline__ void cpasync16(uint32_t dst, const void* src) {
    asm volatile("cp.async.cg.shared.global [%0], [%1], 16;" :: "r"(dst), "l"(src));
}
__device__ __forceinline__ void ldm4(uint32_t (&r)[4], uint32_t addr) {
    asm volatile("ldmatrix.sync.aligned.m8n8.x4.shared.b16 {%0,%1,%2,%3}, [%4];"
                 : "=r"(r[0]), "=r"(r[1]), "=r"(r[2]), "=r"(r[3]) : "r"(addr));
}
__device__ __forceinline__ void mma16816(float (&c)[4], const uint32_t* a,
                                         uint32_t b0, uint32_t b1) {
    asm volatile(
        "mma.sync.aligned.m16n8k16.row.col.f32.bf16.bf16.f32 "
        "{%0,%1,%2,%3}, {%4,%5,%6,%7}, {%8,%9}, {%0,%1,%2,%3};"
        : "+f"(c[0]), "+f"(c[1]), "+f"(c[2]), "+f"(c[3])
        : "r"(a[0]), "r"(a[1]), "r"(a[2]), "r"(a[3]), "r"(b0), "r"(b1));
}
// Tile row = 32 bf16 = 64B; swizzle 16B chunk index within row for conflict-free ldmatrix
__device__ __forceinline__ uint32_t swoff(int row, int kb) {
    return (uint32_t)(row * 64 + ((kb ^ ((row >> 1) & 3)) << 4));
}

constexpr int TILE_BYTES = 128 * 32 * 2;     // 8 KB: 128 rows x 32 bf16
constexpr int STAGES     = 3;
constexpr size_t SMEM_BYTES = (size_t)STAGES * 4 * TILE_BYTES;  // 96 KB -> 2 CTAs/SM

// ---------------- shared GEMM mainloop ----------------
// Computes the 128x128 split-bf16 NT GEMM for one block tile into acc.
__device__ __forceinline__ void gemm_mainloop(
    uint32_t base, int tid, int wid, int lid, int wm, int wn,
    const __nv_bfloat16* aH, const __nv_bfloat16* aL, int lda,
    const __nv_bfloat16* bH, const __nv_bfloat16* bL, int ldb,
    int Kd, float (&acc)[4][4][4])
{
    const __nv_bfloat16* srcs[4] = { aH, aL, bH, bL };
    const int ldsv[4] = { lda, lda, ldb, ldb };

    auto load_chunk = [&](int chunk, int stage) {
        #pragma unroll
        for (int p = 0; p < 4; p++) {
            const __nv_bfloat16* s = srcs[p] + chunk * 32;
            const int ld = ldsv[p];
            const uint32_t tb = base + (uint32_t)((stage * 4 + p) * TILE_BYTES);
            #pragma unroll
            for (int i = 0; i < 2; i++) {
                int o = i * 256 + tid;          // 512 chunks of 16B
                int r = o >> 2, kb = o & 3;
                cpasync16(tb + swoff(r, kb), s + (long)r * ld + kb * 8);
            }
        }
        asm volatile("cp.async.commit_group;" ::: "memory");
    };

    const int nk = Kd / 32;
    load_chunk(0, 0); load_chunk(1, 1);

    const int rA  = (lid & 7) + ((lid >> 3) & 1) * 8;  // ldmatrix row-in-16
    const int kbh = (lid >> 4) & 1;                    // ldmatrix k-half

    int stage = 0;      // stage of chunk k
    int pstage = 2;     // stage of chunk k+2 == stage of chunk k-1

    for (int k = 0; k < nk; k++) {
        if (k + 1 < nk) asm volatile("cp.async.wait_group 1;" ::: "memory");
        else            asm volatile("cp.async.wait_group 0;" ::: "memory");
        __syncthreads();
        // Barrier proves chunk k-1's compute finished everywhere; its stage
        // equals (k+2)%3 — free to refill now. ONE barrier per chunk.
        if (k + 2 < nk) load_chunk(k + 2, pstage);

        const uint32_t sb  = base + (uint32_t)(stage * 4 * TILE_BYTES);
        const uint32_t tAh = sb;
        const uint32_t tAl = sb + TILE_BYTES;
        const uint32_t tBh = sb + 2 * TILE_BYTES;
        const uint32_t tBl = sb + 3 * TILE_BYTES;

        #pragma unroll
        for (int p = 0; p < 2; p++) {            // two k16 steps per 32-chunk
            const uint32_t kxor = (uint32_t)(((2 * p + kbh) ^ ((rA >> 1) & 3)) << 4);
            uint32_t fAh[4][4], fAl[4][4], fBh[2][4], fBl[2][4];

            // hi-plane LDSMs
            #pragma unroll
            for (int i = 0; i < 4; i++) {
                const uint32_t rb = (uint32_t)((wm * 64 + i * 16 + rA) * 64);
                ldm4(fAh[i], tAh + rb + kxor);
            }
            #pragma unroll
            for (int q = 0; q < 2; q++) {
                const uint32_t rb = (uint32_t)((wn * 32 + q * 16 + rA) * 64);
                ldm4(fBh[q], tBh + rb + kxor);
            }
            // pass 1: hh
            #pragma unroll
            for (int i = 0; i < 4; i++)
                #pragma unroll
                for (int nt = 0; nt < 4; nt++) {
                    const int q = nt >> 1, sx = nt & 1;
                    mma16816(acc[i][nt], fAh[i], fBh[q][sx], fBh[q][sx + 2]);
                }
            // lo-plane LDSMs overlap the hh drain
            #pragma unroll
            for (int i = 0; i < 4; i++) {
                const uint32_t rb = (uint32_t)((wm * 64 + i * 16 + rA) * 64);
                ldm4(fAl[i], tAl + rb + kxor);
            }
            #pragma unroll
            for (int q = 0; q < 2; q++) {
                const uint32_t rb = (uint32_t)((wn * 32 + q * 16 + rA) * 64);
                ldm4(fBl[q], tBl + rb + kxor);
            }
            // pass 2: hl
            #pragma unroll
            for (int i = 0; i < 4; i++)
                #pragma unroll
                for (int nt = 0; nt < 4; nt++) {
                    const int q = nt >> 1, sx = nt & 1;
                    mma16816(acc[i][nt], fAh[i], fBl[q][sx], fBl[q][sx + 2]);
                }
            // pass 3: lh
            #pragma unroll
            for (int i = 0; i < 4; i++)
                #pragma unroll
                for (int nt = 0; nt < 4; nt++) {
                    const int q = nt >> 1, sx = nt & 1;
                    mma16816(acc[i][nt], fAl[i], fBh[q][sx], fBh[q][sx + 2]);
                }
        }
        stage  = (stage  == STAGES - 1) ? 0 : stage + 1;
        pstage = (pstage == STAGES - 1) ? 0 : pstage + 1;
    }
}

// ================= generic split-bf16 GEMM (S = QK^T, out = PV) =================
template<int OUTMODE, int BIASMODE>
__global__ void __launch_bounds__(256, 2)
tc_gemm(const __nv_bfloat16* __restrict__ Ah, const __nv_bfloat16* __restrict__ Al,
        int lda, long sA,
        const __nv_bfloat16* __restrict__ Bh, const __nv_bfloat16* __restrict__ Bl,
        int ldb, long sB,
        float* __restrict__ Cf, __nv_bfloat16* __restrict__ Ch, __nv_bfloat16* __restrict__ Cl,
        int ldc, long sC, const float* __restrict__ bias, int Kd)
{
    extern __shared__ __align__(128) char dsm[];
    const uint32_t base = s2u(dsm);
    const int tid = threadIdx.x, wid = tid >> 5, lid = tid & 31;
    const int wm = wid >> 2, wn = wid & 3;
    const int m0 = blockIdx.y * 128, n0 = blockIdx.x * 128;
    const long z = blockIdx.z;

    float acc[4][4][4];
    #pragma unroll
    for (int i = 0; i < 4; i++)
        #pragma unroll
        for (int t = 0; t < 4; t++)
            #pragma unroll
            for (int j = 0; j < 4; j++) acc[i][t][j] = 0.0f;

    gemm_mainloop(base, tid, wid, lid, wm, wn,
                  Ah + z * sA + (long)m0 * lda, Al + z * sA + (long)m0 * lda, lda,
                  Bh + z * sB + (long)n0 * ldb, Bl + z * sB + (long)n0 * ldb, ldb,
                  Kd, acc);

    #pragma unroll
    for (int i = 0; i < 4; i++)
        #pragma unroll
        for (int nt = 0; nt < 4; nt++) {
            const int row = m0 + wm * 64 + i * 16 + (lid >> 2);
            const int col = n0 + wn * 32 + nt * 8 + 2 * (lid & 3);
            float v0 = acc[i][nt][0], v1 = acc[i][nt][1];
            float v2 = acc[i][nt][2], v3 = acc[i][nt][3];
            if (BIASMODE == 1) {
                const float b0 = bias[col], b1 = bias[col + 1];
                v0 += b0; v1 += b1; v2 += b0; v3 += b1;
            }
            const long o0 = (long)row * ldc + col + z * sC;
            const long o1 = o0 + 8L * ldc;
            if (OUTMODE == 0) {
                *(float2*)(Cf + o0) = make_float2(v0, v1);
                *(float2*)(Cf + o1) = make_float2(v2, v3);
            } else {
                __nv_bfloat16 h0 = __float2bfloat16(v0), h1 = __float2bfloat16(v1);
                __nv_bfloat16 h2 = __float2bfloat16(v2), h3 = __float2bfloat16(v3);
                __nv_bfloat16 l0 = __float2bfloat16(v0 - __bfloat162float(h0));
                __nv_bfloat16 l1 = __float2bfloat16(v1 - __bfloat162float(h1));
                __nv_bfloat16 l2 = __float2bfloat16(v2 - __bfloat162float(h2));
                __nv_bfloat16 l3 = __float2bfloat16(v3 - __bfloat162float(h3));
                __nv_bfloat162 ph0; ph0.x = h0; ph0.y = h1;
                __nv_bfloat162 ph1; ph1.x = h2; ph1.y = h3;
                __nv_bfloat162 pl0; pl0.x = l0; pl0.y = l1;
                __nv_bfloat162 pl1; pl1.x = l2; pl1.y = l3;
                *(__nv_bfloat162*)(Ch + o0) = ph0;
                *(__nv_bfloat162*)(Ch + o1) = ph1;
                *(__nv_bfloat162*)(Cl + o0) = pl0;
                *(__nv_bfloat162*)(Cl + o1) = pl1;
            }
        }
}

// ===== fused QKV projection: one launch; z=0 -> Q, z=1 -> K, z=2 -> V^T =======
__global__ void __launch_bounds__(256, 2)
qkv_gemm(const __nv_bfloat16* __restrict__ Xh, const __nv_bfloat16* __restrict__ Xl,
         const __nv_bfloat16* __restrict__ Wqh, const __nv_bfloat16* __restrict__ Wql,
         const __nv_bfloat16* __restrict__ Wkh, const __nv_bfloat16* __restrict__ Wkl,
         const __nv_bfloat16* __restrict__ Wvh, const __nv_bfloat16* __restrict__ Wvl,
         const float* __restrict__ bq, const float* __restrict__ bk,
         const float* __restrict__ bv,
         __nv_bfloat16* __restrict__ Qh, __nv_bfloat16* __restrict__ Ql,
         __nv_bfloat16* __restrict__ Kh, __nv_bfloat16* __restrict__ Kl,
         __nv_bfloat16* __restrict__ Vth, __nv_bfloat16* __restrict__ Vtl)
{
    extern __shared__ __align__(128) char dsm[];
    const uint32_t base = s2u(dsm);
    const int tid = threadIdx.x, wid = tid >> 5, lid = tid & 31;
    const int wm = wid >> 2, wn = wid & 3;
    const int zz = blockIdx.z;

    float acc[4][4][4];
    #pragma unroll
    for (int i = 0; i < 4; i++)
        #pragma unroll
        for (int t = 0; t < 4; t++)
            #pragma unroll
            for (int j = 0; j < 4; j++) acc[i][t][j] = 0.0f;

    if (zz < 2) {
        const __nv_bfloat16* Bh = (zz == 0) ? Wqh : Wkh;
        const __nv_bfloat16* Bl = (zz == 0) ? Wql : Wkl;
        const float* bias       = (zz == 0) ? bq  : bk;
        __nv_bfloat16* Ch       = (zz == 0) ? Qh  : Kh;
        __nv_bfloat16* Cl       = (zz == 0) ? Ql  : Kl;
        const int m0 = blockIdx.y * 128, n0 = blockIdx.x * 128;

        gemm_mainloop(base, tid, wid, lid, wm, wn,
                      Xh + (long)m0 * D_, Xl + (long)m0 * D_, D_,
                      Bh + (long)n0 * D_, Bl + (long)n0 * D_, D_,
                      D_, acc);

        #pragma unroll
        for (int i = 0; i < 4; i++)
            #pragma unroll
            for (int nt = 0; nt < 4; nt++) {
                const int row = m0 + wm * 64 + i * 16 + (lid >> 2);
                const int col = n0 + wn * 32 + nt * 8 + 2 * (lid & 3);
                const float b0 = bias[col], b1 = bias[col + 1];
                float v0 = acc[i][nt][0] + b0, v1 = acc[i][nt][1] + b1;
                float v2 = acc[i][nt][2] + b0, v3 = acc[i][nt][3] + b1;
                const long o0 = (long)row * D_ + col;
                const long o1 = o0 + 8L * D_;
                __nv_bfloat16 h0 = __float2bfloat16(v0), h1 = __float2bfloat16(v1);
                __nv_bfloat16 h2 = __float2bfloat16(v2), h3 = __float2bfloat16(v3);
                __nv_bfloat16 l0 = __float2bfloat16(v0 - __bfloat162float(h0));
                __nv_bfloat16 l1 = __float2bfloat16(v1 - __bfloat162float(h1));
                __nv_bfloat16 l2 = __float2bfloat16(v2 - __bfloat162float(h2));
                __nv_bfloat16 l3 = __float2bfloat16(v3 - __bfloat162float(h3));
                __nv_bfloat162 ph0; ph0.x = h0; ph0.y = h1;
                __nv_bfloat162 ph1; ph1.x = h2; ph1.y = h3;
                __nv_bfloat162 pl0; pl0.x = l0; pl0.y = l1;
                __nv_bfloat162 pl1; pl1.x = l2; pl1.y = l3;
                *(__nv_bfloat162*)(Ch + o0) = ph0;
                *(__nv_bfloat162*)(Ch + o1) = ph1;
                *(__nv_bfloat162*)(Cl + o0) = pl0;
                *(__nv_bfloat162*)(Cl + o1) = pl1;
            }
    } else {
        // V^T slice: A = Wv^T (e-tiles on grid x), B = X (m-tiles on grid y)
        const int m0 = blockIdx.x * 128;     // e dimension (only 8 tiles)
        const int n0 = blockIdx.y * 128;     // m dimension (64 tiles)

        gemm_mainloop(base, tid, wid, lid, wm, wn,
                      Wvh + (long)m0 * D_, Wvl + (long)m0 * D_, D_,
                      Xh  + (long)n0 * D_, Xl  + (long)n0 * D_, D_,
                      D_, acc);

        #pragma unroll
        for (int i = 0; i < 4; i++)
            #pragma unroll
            for (int nt = 0; nt < 4; nt++) {
                const int row = m0 + wm * 64 + i * 16 + (lid >> 2);   // e
                const int col = n0 + wn * 32 + nt * 8 + 2 * (lid & 3); // m
                const float b0 = bv[row], b1 = bv[row + 8];
                float v0 = acc[i][nt][0] + b0, v1 = acc[i][nt][1] + b0;
                float v2 = acc[i][nt][2] + b1, v3 = acc[i][nt][3] + b1;
                const long o0 = (long)row * MTOT + col;
                const long o1 = o0 + 8L * MTOT;
                __nv_bfloat16 h0 = __float2bfloat16(v0), h1 = __float2bfloat16(v1);
                __nv_bfloat16 h2 = __float2bfloat16(v2), h3 = __float2bfloat16(v3);
                __nv_bfloat16 l0 = __float2bfloat16(v0 - __bfloat162float(h0));
                __nv_bfloat16 l1 = __float2bfloat16(v1 - __bfloat162float(h1));
                __nv_bfloat16 l2 = __float2bfloat16(v2 - __bfloat162float(h2));
                __nv_bfloat16 l3 = __float2bfloat16(v3 - __bfloat162float(h3));
                __nv_bfloat162 ph0; ph0.x = h0; ph0.y = h1;
                __nv_bfloat162 ph1; ph1.x = h2; ph1.y = h3;
                __nv_bfloat162 pl0; pl0.x = l0; pl0.y = l1;
                __nv_bfloat162 pl1; pl1.x = l2; pl1.y = l3;
                *(__nv_bfloat162*)(Vth + o0) = ph0;
                *(__nv_bfloat162*)(Vth + o1) = ph1;
                *(__nv_bfloat162*)(Vtl + o0) = pl0;
                *(__nv_bfloat162*)(Vtl + o1) = pl1;
            }
    }
}

// ================= merged prep: z<3 -> weight transpose+split, z==3 -> X split
__global__ void __launch_bounds__(256)
prep_kernel(const float* __restrict__ X,
            const float* __restrict__ W0, const float* __restrict__ W1,
            const float* __restrict__ W2,
            __nv_bfloat16* __restrict__ Xh, __nv_bfloat16* __restrict__ Xl,
            __nv_bfloat16* __restrict__ T0h, __nv_bfloat16* __restrict__ T0l,
            __nv_bfloat16* __restrict__ T1h, __nv_bfloat16* __restrict__ T1l,
            __nv_bfloat16* __restrict__ T2h, __nv_bfloat16* __restrict__ T2l)
{
    const int tid = threadIdx.x;

    if (blockIdx.z == 3) {
        // X split: 1024 blocks x 8 chunks x 256 threads x 4 floats = 8192*1024
        const int b = blockIdx.y * 32 + blockIdx.x;    // 0..1023
        #pragma unroll
        for (int j = 0; j < 8; j++) {
            const long i = (((long)b * 8 + j) * 256 + tid) * 4;
            float4 v = *(const float4*)(X + i);
            float vv[4] = { v.x, v.y, v.z, v.w };
            __nv_bfloat16 h[4], l[4];
            #pragma unroll
            for (int t = 0; t < 4; t++) {
                h[t] = __float2bfloat16(vv[t]);
                l[t] = __float2bfloat16(vv[t] - __bfloat162float(h[t]));
            }
            __nv_bfloat162 h01, h23, l01, l23;
            h01.x = h[0]; h01.y = h[1]; h23.x = h[2]; h23.y = h[3];
            l01.x = l[0]; l01.y = l[1]; l23.x = l[2]; l23.y = l[3];
            *(__nv_bfloat162*)(Xh + i)     = h01;
            *(__nv_bfloat162*)(Xh + i + 2) = h23;
            *(__nv_bfloat162*)(Xl + i)     = l01;
            *(__nv_bfloat162*)(Xl + i + 2) = l23;
        }
        return;
    }

    // Weight transpose+split: T[e][d] = W[d][e]
    __shared__ float t[32][33];
    const float* W = (blockIdx.z == 0) ? W0 : (blockIdx.z == 1) ? W1 : W2;
    __nv_bfloat16* Th = (blockIdx.z == 0) ? T0h : (blockIdx.z == 1) ? T1h : T2h;
    __nv_bfloat16* Tl = (blockIdx.z == 0) ? T0l : (blockIdx.z == 1) ? T1l : T2l;

    const int tx = tid & 31, ty = tid >> 5;            // 32 x 8
    const int e = blockIdx.x * 32 + tx;
    const int d0 = blockIdx.y * 32;
    #pragma unroll
    for (int i = ty; i < 32; i += 8)
        t[i][tx] = W[(long)(d0 + i) * D_ + e];
    __syncthreads();
    const int eo = blockIdx.x * 32;
    const int d = d0 + tx;
    #pragma unroll
    for (int i = ty; i < 32; i += 8) {
        float w = t[tx][i];
        __nv_bfloat16 h = __float2bfloat16(w);
        __nv_bfloat16 l = __float2bfloat16(w - __bfloat162float(h));
        Th[(long)(eo + i) * D_ + d] = h;
        Tl[(long)(eo + i) * D_ + d] = l;
    }
}

// Row softmax over S (length 2048), vectorized float4 I/O, split-bf16 P out.
// Thread t owns columns [4t, 4t+3] and [4t+1024, 4t+1027] — coalesced 16B lanes.
__global__ void __launch_bounds__(256)
softmax_split_kernel(const float* __restrict__ S, __nv_bfloat16* __restrict__ Ph,
                     __nv_bfloat16* __restrict__ Pl)
{
    const long row = blockIdx.x;
    const float* p = S + row * (long)N_;
    const int tid = threadIdx.x;
    const int c0 = tid * 4;

    float4 a0 = *(const float4*)(p + c0);
    float4 a1 = *(const float4*)(p + c0 + 1024);
    float v[8] = { a0.x, a0.y, a0.z, a0.w, a1.x, a1.y, a1.z, a1.w };

    float mx = v[0];
    #pragma unroll
    for (int i = 1; i < 8; i++) mx = fmaxf(mx, v[i]);

    __shared__ float redm[8], reds[8];
    #pragma unroll
    for (int o = 16; o; o >>= 1) mx = fmaxf(mx, __shfl_xor_sync(0xffffffffu, mx, o));
    if ((tid & 31) == 0) redm[tid >> 5] = mx;
    __syncthreads();
    if (tid == 0) {
        float m = redm[0];
        #pragma unroll
        for (int i = 1; i < 8; i++) m = fmaxf(m, redm[i]);
        redm[0] = m;
    }
    __syncthreads();
    mx = redm[0];

    float s = 0.0f;
    #pragma unroll
    for (int i = 0; i < 8; i++) { v[i] = __expf(v[i] - mx); s += v[i]; }
    #pragma unroll
    for (int o = 16; o; o >>= 1) s += __shfl_xor_sync(0xffffffffu, s, o);
    if ((tid & 31) == 0) reds[tid >> 5] = s;
    __syncthreads();
    if (tid == 0) {
        float m = 0.0f;
        #pragma unroll
        for (int i = 0; i < 8; i++) m += reds[i];
        reds[0] = m;
    }
    __syncthreads();
    const float inv = 1.0f / reds[0];

    const long rb = row * (long)N_;
    #pragma unroll
    for (int g = 0; g < 2; g++) {
        const long o = rb + c0 + g * 1024;
        float w0 = v[4*g+0] * inv, w1 = v[4*g+1] * inv;
        float w2 = v[4*g+2] * inv, w3 = v[4*g+3] * inv;
        __nv_bfloat16 h0 = __float2bfloat16(w0), h1 = __float2bfloat16(w1);
        __nv_bfloat16 h2 = __float2bfloat16(w2), h3 = __float2bfloat16(w3);
        __nv_bfloat16 l0 = __float2bfloat16(w0 - __bfloat162float(h0));
        __nv_bfloat16 l1 = __float2bfloat16(w1 - __bfloat162float(h1));
        __nv_bfloat16 l2 = __float2bfloat16(w2 - __bfloat162float(h2));
        __nv_bfloat16 l3 = __float2bfloat16(w3 - __bfloat162float(h3));
        __nv_bfloat162 ph0; ph0.x = h0; ph0.y = h1;
        __nv_bfloat162 ph1; ph1.x = h2; ph1.y = h3;
        __nv_bfloat162 pl0; pl0.x = l0; pl0.y = l1;
        __nv_bfloat162 pl1; pl1.x = l2; pl1.y = l3;
        *(__nv_bfloat162*)(Ph + o)     = ph0;
        *(__nv_bfloat162*)(Ph + o + 2) = ph1;
        *(__nv_bfloat162*)(Pl + o)     = pl0;
        *(__nv_bfloat162*)(Pl + o + 2) = pl1;
    }
}

// ================= host glue =================
extern "C" void kernel_launch(void* const* d_in, const int* in_sizes, int n_in,
                              void* d_out, int out_size)
{
    const float* X  = (const float*)d_in[0];
    const float* Wq = (const float*)d_in[1];
    const float* bq = (const float*)d_in[2];
    const float* Wk = (const float*)d_in[3];
    const float* bk = (const float*)d_in[4];
    const float* Wv = (const float*)d_in[5];
    const float* bv = (const float*)d_in[6];
    float* out = (float*)d_out;

    __nv_bfloat16 *Xh, *Xl, *Qh, *Ql, *Kh, *Kl, *Vth, *Vtl;
    __nv_bfloat16 *Wqth, *Wqtl, *Wkth, *Wktl, *Wvth, *Wvtl, *Ph, *Pl;
    float* S;
    cudaGetSymbolAddress((void**)&Xh, g_Xh);   cudaGetSymbolAddress((void**)&Xl, g_Xl);
    cudaGetSymbolAddress((void**)&Qh, g_Qh);   cudaGetSymbolAddress((void**)&Ql, g_Ql);
    cudaGetSymbolAddress((void**)&Kh, g_Kh);   cudaGetSymbolAddress((void**)&Kl, g_Kl);
    cudaGetSymbolAddress((void**)&Vth, g_Vth); cudaGetSymbolAddress((void**)&Vtl, g_Vtl);
    cudaGetSymbolAddress((void**)&Wqth, g_Wqth); cudaGetSymbolAddress((void**)&Wqtl, g_Wqtl);
    cudaGetSymbolAddress((void**)&Wkth, g_Wkth); cudaGetSymbolAddress((void**)&Wktl, g_Wktl);
    cudaGetSymbolAddress((void**)&Wvth, g_Wvth); cudaGetSymbolAddress((void**)&Wvtl, g_Wvtl);
    cudaGetSymbolAddress((void**)&Ph, g_Ph);   cudaGetSymbolAddress((void**)&Pl, g_Pl);
    cudaGetSymbolAddress((void**)&S, g_S);

    cudaFuncSetAttribute((const void*)qkv_gemm,      cudaFuncAttributeMaxDynamicSharedMemorySize, (int)SMEM_BYTES);
    cudaFuncSetAttribute((const void*)tc_gemm<0, 0>, cudaFuncAttributeMaxDynamicSharedMemorySize, (int)SMEM_BYTES);

    dim3 blk(256);

    // 0) merged prep: X split + weight transpose/split in ONE launch
    prep_kernel<<<dim3(32, 32, 4), blk>>>(
        X, Wq, Wk, Wv, Xh, Xl, Wqth, Wqtl, Wkth, Wktl, Wvth, Wvtl);

    // 1) fused QKV projection: one launch; z=2 emits V^T directly
    qkv_gemm<<<dim3(8, 64, 3), blk, SMEM_BYTES>>>(
        Xh, Xl, Wqth, Wqtl, Wkth, Wktl, Wvth, Wvtl,
        bq, bk, bv, Qh, Ql, Kh, Kl, Vth, Vtl);

    // 2) S = Q K^T per batch (fp32)
    tc_gemm<0, 0><<<dim3(16, 16, B_), blk, SMEM_BYTES>>>(
        Qh, Ql, D_, (long)N_ * D_, Kh, Kl, D_, (long)N_ * D_,
        S, nullptr, nullptr, N_, (long)N_ * N_, nullptr, D_);

    // 3) softmax + split P (vectorized)
    softmax_split_kernel<<<B_ * N_, 256>>>(S, Ph, Pl);

    // 4) out = P V per batch (NT against V^T, fp32 out)
    tc_gemm<0, 0><<<dim3(8, 16, B_), blk, SMEM_BYTES>>>(
        Ph, Pl, N_, (long)N_ * N_, Vth, Vtl, MTOT, (long)N_,
        out, nullptr, nullptr, D_, (long)N_ * D_, nullptr, N_);
}